// round 1
// baseline (speedup 1.0000x reference)
#include <cuda_runtime.h>
#include <cuda_bf16.h>
#include <math.h>

#define TOKENS 4096      // B*S = 2*2048
#define S_LEN  2048
#define HDIM   1024
#define NH     16
#define HD     64

// Scratch (static device globals — no allocations allowed)
__device__ float g_qkv[(size_t)TOKENS * 3 * HDIM];  // [token][3*1024]: q|k|v
__device__ float g_att[(size_t)TOKENS * HDIM];      // attention output

// ---------------------------------------------------------------------------
// GEMM: C[M,N] = A[M,K] @ B[N,K]^T   (A,B,C row-major; all dims % 128/8 == 0)
// 128x128 tile, BK=8, 256 threads, 8x8 per-thread register block.
// ---------------------------------------------------------------------------
__global__ void __launch_bounds__(256) sgemm_nt(const float* __restrict__ A,
                                                const float* __restrict__ B,
                                                float* __restrict__ C,
                                                int M, int N, int K) {
    __shared__ float As[8][132];
    __shared__ float Bs[8][132];
    const int tid  = threadIdx.x;
    const int trow = (tid >> 4) << 3;   // 0..120
    const int tcol = (tid & 15) << 3;   // 0..120
    const int lRow = tid >> 1;          // 0..127
    const int lCol = (tid & 1) << 2;    // 0 or 4

    const float* Ap = A + (size_t)(blockIdx.y * 128 + lRow) * K + lCol;
    const float* Bp = B + (size_t)(blockIdx.x * 128 + lRow) * K + lCol;

    float acc[8][8] = {};

    for (int k0 = 0; k0 < K; k0 += 8) {
        float4 av = *(const float4*)(Ap + k0);
        float4 bv = *(const float4*)(Bp + k0);
        As[lCol + 0][lRow] = av.x; As[lCol + 1][lRow] = av.y;
        As[lCol + 2][lRow] = av.z; As[lCol + 3][lRow] = av.w;
        Bs[lCol + 0][lRow] = bv.x; Bs[lCol + 1][lRow] = bv.y;
        Bs[lCol + 2][lRow] = bv.z; Bs[lCol + 3][lRow] = bv.w;
        __syncthreads();
        #pragma unroll
        for (int kk = 0; kk < 8; kk++) {
            float a[8], b[8];
            *(float4*)(a)     = *(const float4*)&As[kk][trow];
            *(float4*)(a + 4) = *(const float4*)&As[kk][trow + 4];
            *(float4*)(b)     = *(const float4*)&Bs[kk][tcol];
            *(float4*)(b + 4) = *(const float4*)&Bs[kk][tcol + 4];
            #pragma unroll
            for (int i = 0; i < 8; i++)
                #pragma unroll
                for (int j = 0; j < 8; j++)
                    acc[i][j] = fmaf(a[i], b[j], acc[i][j]);
        }
        __syncthreads();
    }

    float* Cp = C + (size_t)(blockIdx.y * 128 + trow) * N + blockIdx.x * 128 + tcol;
    #pragma unroll
    for (int i = 0; i < 8; i++) {
        *(float4*)(Cp + (size_t)i * N)     = make_float4(acc[i][0], acc[i][1], acc[i][2], acc[i][3]);
        *(float4*)(Cp + (size_t)i * N + 4) = make_float4(acc[i][4], acc[i][5], acc[i][6], acc[i][7]);
    }
}

// ---------------------------------------------------------------------------
// RoPE applied in-place to q and k slices of g_qkv.
// One thread per (token, head, i) with i in [0,32): rotates dims (i, i+32).
// inv_freq computed in double then cast to fp32 to match jax fp32 semantics.
// ---------------------------------------------------------------------------
__global__ void rope_kernel(float* __restrict__ qkv) {
    int idx = blockIdx.x * blockDim.x + threadIdx.x;
    if (idx >= TOKENS * NH * 32) return;
    int i     = idx & 31;
    int h     = (idx >> 5) & 15;
    int token = idx >> 9;
    int s     = token & (S_LEN - 1);

    double invf_d = exp(-((double)i / 32.0) * log(10000.0));
    float  invf   = (float)invf_d;
    float  ang    = (float)s * invf;
    float  c = cosf(ang), sn = sinf(ang);

    size_t base = (size_t)token * (3 * HDIM) + h * HD;
    // q
    float q1 = qkv[base + i], q2 = qkv[base + i + 32];
    qkv[base + i]      = q1 * c - q2 * sn;
    qkv[base + i + 32] = q2 * c + q1 * sn;
    // k
    float k1 = qkv[base + HDIM + i], k2 = qkv[base + HDIM + i + 32];
    qkv[base + HDIM + i]      = k1 * c - k2 * sn;
    qkv[base + HDIM + i + 32] = k2 * c + k1 * sn;
}

// ---------------------------------------------------------------------------
// Flash attention (fp32, causal). One block = 64 q-rows of one (batch, head).
// 256 threads: ty=tid/16 owns rows ty*4..+3, tx=tid%16 owns cols/dims tx*4..+3.
// Online softmax; KV streamed in 64-row tiles up to the causal bound.
// ---------------------------------------------------------------------------
#define SM_STRIDE 68
#define QS(d, r) Qs[(d) * SM_STRIDE + (r)]
#define KS(d, c) Ks[(d) * SM_STRIDE + (c)]
#define VS(j, d) Vs[(j) * SM_STRIDE + (d)]
#define PS(j, r) Ps[(j) * SM_STRIDE + (r)]

__global__ void __launch_bounds__(256) flash_kernel(const float* __restrict__ qkv,
                                                    float* __restrict__ out) {
    extern __shared__ float smf[];
    float* Qs = smf;                      // [64][68], transposed: [d][row]
    float* Ks = smf + 64 * SM_STRIDE;     // [64][68], transposed: [d][col]
    float* Vs = smf + 2 * 64 * SM_STRIDE; // [64][68], natural:    [j][d]
    float* Ps = smf + 3 * 64 * SM_STRIDE; // [64][68], transposed: [j][row]

    const int qb  = blockIdx.x;           // q tile 0..31
    const int b   = blockIdx.y >> 4;
    const int h   = blockIdx.y & 15;
    const int tid = threadIdx.x;
    const int ty  = tid >> 4, tx = tid & 15;
    const int row0 = ty << 2, col0 = tx << 2;

    // Load Q tile (scaled by 1/sqrt(hd)=0.125), store transposed
    for (int i = tid; i < 64 * 16; i += 256) {
        int r  = i >> 4;
        int dg = (i & 15) << 2;
        const float4 v = *(const float4*)(qkv + (size_t)(b * S_LEN + qb * 64 + r) * (3 * HDIM) + h * HD + dg);
        QS(dg + 0, r) = v.x * 0.125f; QS(dg + 1, r) = v.y * 0.125f;
        QS(dg + 2, r) = v.z * 0.125f; QS(dg + 3, r) = v.w * 0.125f;
    }

    float acc[4][4] = {};
    float m_i[4], l_i[4];
    #pragma unroll
    for (int i = 0; i < 4; i++) { m_i[i] = -1e30f; l_i[i] = 0.f; }

    for (int jb = 0; jb <= qb; jb++) {
        // Load K (transposed) and V (natural) tiles
        for (int i = tid; i < 64 * 16; i += 256) {
            int c  = i >> 4;
            int dg = (i & 15) << 2;
            size_t base = (size_t)(b * S_LEN + jb * 64 + c) * (3 * HDIM) + h * HD + dg;
            float4 kv4 = *(const float4*)(qkv + HDIM + base);
            KS(dg + 0, c) = kv4.x; KS(dg + 1, c) = kv4.y;
            KS(dg + 2, c) = kv4.z; KS(dg + 3, c) = kv4.w;
            *(float4*)&VS(c, dg) = *(const float4*)(qkv + 2 * HDIM + base);
        }
        __syncthreads();

        // S = Q @ K^T (already scaled)
        float s[4][4] = {};
        #pragma unroll 8
        for (int d = 0; d < 64; d++) {
            float qf[4], kf[4];
            *(float4*)qf = *(const float4*)&QS(d, row0);
            *(float4*)kf = *(const float4*)&KS(d, col0);
            #pragma unroll
            for (int i = 0; i < 4; i++)
                #pragma unroll
                for (int j = 0; j < 4; j++)
                    s[i][j] = fmaf(qf[i], kf[j], s[i][j]);
        }

        // Causal mask on diagonal tile
        if (jb == qb) {
            #pragma unroll
            for (int i = 0; i < 4; i++)
                #pragma unroll
                for (int j = 0; j < 4; j++)
                    if (col0 + j > row0 + i) s[i][j] = -1e30f;
        }

        // Online softmax update (row stats reduced over the 16 tx lanes)
        #pragma unroll
        for (int i = 0; i < 4; i++) {
            float mx = fmaxf(fmaxf(s[i][0], s[i][1]), fmaxf(s[i][2], s[i][3]));
            #pragma unroll
            for (int off = 1; off < 16; off <<= 1)
                mx = fmaxf(mx, __shfl_xor_sync(0xffffffffu, mx, off));
            float m_new = fmaxf(m_i[i], mx);
            float alpha = expf(m_i[i] - m_new);
            float rs = 0.f;
            #pragma unroll
            for (int j = 0; j < 4; j++) {
                float p = expf(s[i][j] - m_new);
                rs += p;
                PS(col0 + j, row0 + i) = p;
            }
            #pragma unroll
            for (int off = 1; off < 16; off <<= 1)
                rs += __shfl_xor_sync(0xffffffffu, rs, off);
            l_i[i] = l_i[i] * alpha + rs;
            m_i[i] = m_new;
            #pragma unroll
            for (int j = 0; j < 4; j++) acc[i][j] *= alpha;
        }
        __syncthreads();

        // acc += P @ V
        #pragma unroll 8
        for (int j = 0; j < 64; j++) {
            float pf[4], vf[4];
            *(float4*)pf = *(const float4*)&PS(j, row0);
            *(float4*)vf = *(const float4*)&VS(j, col0);
            #pragma unroll
            for (int i = 0; i < 4; i++)
                #pragma unroll
                for (int d = 0; d < 4; d++)
                    acc[i][d] = fmaf(pf[i], vf[d], acc[i][d]);
        }
        __syncthreads();
    }

    // Normalize and write out: out[token][h*64 + d]
    #pragma unroll
    for (int i = 0; i < 4; i++) {
        float inv = 1.f / l_i[i];
        int token = b * S_LEN + qb * 64 + row0 + i;
        float4 o = make_float4(acc[i][0] * inv, acc[i][1] * inv,
                               acc[i][2] * inv, acc[i][3] * inv);
        *(float4*)(out + (size_t)token * HDIM + h * HD + col0) = o;
    }
}

// ---------------------------------------------------------------------------
// Launch
// ---------------------------------------------------------------------------
extern "C" void kernel_launch(void* const* d_in, const int* in_sizes, int n_in,
                              void* d_out, int out_size) {
    const float* x     = (const float*)d_in[0];
    const float* w_qkv = (const float*)d_in[1];
    const float* w_o   = (const float*)d_in[2];
    float* out = (float*)d_out;

    float *qkv, *att;
    cudaGetSymbolAddress((void**)&qkv, g_qkv);
    cudaGetSymbolAddress((void**)&att, g_att);

    // 1) QKV projection: [4096,3072] = x[4096,1024] @ w_qkv[3072,1024]^T
    sgemm_nt<<<dim3(3 * HDIM / 128, TOKENS / 128), 256>>>(x, w_qkv, qkv, TOKENS, 3 * HDIM, HDIM);

    // 2) RoPE on q,k in place
    rope_kernel<<<(TOKENS * NH * 32) / 256, 256>>>(qkv);

    // 3) Causal flash attention -> att[4096,1024]
    const int flash_smem = 4 * 64 * SM_STRIDE * (int)sizeof(float);  // 69632 B
    cudaFuncSetAttribute(flash_kernel, cudaFuncAttributeMaxDynamicSharedMemorySize, flash_smem);
    flash_kernel<<<dim3(S_LEN / 64, 2 * NH), 256, flash_smem>>>(qkv, att);

    // 4) Output projection: out[4096,1024] = att @ w_o[1024,1024]^T
    sgemm_nt<<<dim3(HDIM / 128, TOKENS / 128), 256>>>(att, w_o, out, TOKENS, HDIM, HDIM);
}

// round 3
// speedup vs baseline: 2.5145x; 2.5145x over previous
#include <cuda_runtime.h>
#include <math.h>

#define TOKENS 4096      // B*S = 2*2048
#define S_LEN  2048
#define HDIM   1024
#define NH     16

// Scratch (static device globals — no allocations allowed)
__device__ float g_qkv[(size_t)TOKENS * 3 * HDIM];  // [token][3*1024]: q|k|v
__device__ float g_att[(size_t)TOKENS * HDIM];      // attention output

// ---------------------------------------------------------------------------
// Helpers: tf32 conversion, m16n8k8 tf32 MMA, fast exp2 on the FMA pipe
// ---------------------------------------------------------------------------
__device__ __forceinline__ unsigned f2tf(float x) {
    unsigned r; asm("cvt.rna.tf32.f32 %0, %1;" : "=r"(r) : "f"(x)); return r;
}
__device__ __forceinline__ float f2tff(float x) { return __uint_as_float(f2tf(x)); }

__device__ __forceinline__ void mma8(float* c, const unsigned* a, const unsigned* b) {
    asm("mma.sync.aligned.m16n8k8.row.col.f32.tf32.tf32.f32 "
        "{%0,%1,%2,%3}, {%4,%5,%6,%7}, {%8,%9}, {%0,%1,%2,%3};"
        : "+f"(c[0]), "+f"(c[1]), "+f"(c[2]), "+f"(c[3])
        : "r"(a[0]), "r"(a[1]), "r"(a[2]), "r"(a[3]), "r"(b[0]), "r"(b[1]));
}

// 2^t via round + degree-6 poly + exponent splice. No MUFU. ~1e-7 rel err.
__device__ __forceinline__ float fexp2(float t) {
    t = fmaxf(t, -126.0f);
    float r  = __fadd_rn(t, 12582912.0f);            // round-to-nearest int
    int   n  = __float_as_int(r) - 0x4B400000;
    float f  = t - __fadd_rn(r, -12582912.0f);       // f in [-0.5, 0.5]
    float p  = 1.535336188319500e-4f;
    p = fmaf(p, f, 1.339887440266574e-3f);
    p = fmaf(p, f, 9.618437357674640e-3f);
    p = fmaf(p, f, 5.550332471162809e-2f);
    p = fmaf(p, f, 2.402264791363012e-1f);
    p = fmaf(p, f, 6.931472028550421e-1f);
    p = fmaf(p, f, 1.0f);
    return p * __int_as_float((n + 127) << 23);
}

// ---------------------------------------------------------------------------
// tf32 tensor-core GEMM: C[M,N] = A[M,K] @ B[N,K]^T, all row-major.
// 128x128 block tile, BK=16, 8 warps (2x4), warp tile 64x32, m16n8k8 frags.
// Smem [row][k] with stride 20 -> fragment LDS bank = (4*row + k) % 32,
// bijective over the (lane/4, lane%4) pattern => conflict-free.
// ---------------------------------------------------------------------------
#define GS 20
__global__ void __launch_bounds__(256) gemm_tf32_nt(
        const float* __restrict__ A, const float* __restrict__ B,
        float* __restrict__ C, int M, int N, int K) {
    __shared__ float As[128][GS];
    __shared__ float Bs[128][GS];
    const int tid  = threadIdx.x, lane = tid & 31;
    const int wid  = tid >> 5, wm = wid >> 2, wn = wid & 3;   // warps 2(M) x 4(N)
    const int g    = lane >> 2, q = lane & 3;
    const int ldR  = tid >> 2, ldC = (tid & 3) << 2;          // 64 rows x 16 cols, x2 rows

    const float* Ag = A + (size_t)(blockIdx.y * 128 + ldR) * K + ldC;
    const float* Bg = B + (size_t)(blockIdx.x * 128 + ldR) * K + ldC;

    float acc[4][4][4] = {};

    float4 ra0 = *(const float4*)Ag;
    float4 ra1 = *(const float4*)(Ag + (size_t)64 * K);
    float4 rb0 = *(const float4*)Bg;
    float4 rb1 = *(const float4*)(Bg + (size_t)64 * K);

    const int nC = K >> 4;
    for (int ch = 0; ch < nC; ch++) {
        *(float4*)&As[ldR][ldC]      = make_float4(f2tff(ra0.x), f2tff(ra0.y), f2tff(ra0.z), f2tff(ra0.w));
        *(float4*)&As[ldR + 64][ldC] = make_float4(f2tff(ra1.x), f2tff(ra1.y), f2tff(ra1.z), f2tff(ra1.w));
        *(float4*)&Bs[ldR][ldC]      = make_float4(f2tff(rb0.x), f2tff(rb0.y), f2tff(rb0.z), f2tff(rb0.w));
        *(float4*)&Bs[ldR + 64][ldC] = make_float4(f2tff(rb1.x), f2tff(rb1.y), f2tff(rb1.z), f2tff(rb1.w));
        __syncthreads();

        Ag += 16; Bg += 16;
        if (ch + 1 < nC) {
            ra0 = *(const float4*)Ag;
            ra1 = *(const float4*)(Ag + (size_t)64 * K);
            rb0 = *(const float4*)Bg;
            rb1 = *(const float4*)(Bg + (size_t)64 * K);
        }

        #pragma unroll
        for (int kk = 0; kk < 2; kk++) {
            unsigned af[4][4], bf[4][2];
            const int cb = kk * 8 + q;
            #pragma unroll
            for (int mi = 0; mi < 4; mi++) {
                const int rb = wm * 64 + mi * 16;
                af[mi][0] = __float_as_uint(As[rb + g][cb]);
                af[mi][1] = __float_as_uint(As[rb + 8 + g][cb]);
                af[mi][2] = __float_as_uint(As[rb + g][cb + 4]);
                af[mi][3] = __float_as_uint(As[rb + 8 + g][cb + 4]);
            }
            #pragma unroll
            for (int ni = 0; ni < 4; ni++) {
                const int nb = wn * 32 + ni * 8;
                bf[ni][0] = __float_as_uint(Bs[nb + g][cb]);
                bf[ni][1] = __float_as_uint(Bs[nb + g][cb + 4]);
            }
            #pragma unroll
            for (int mi = 0; mi < 4; mi++)
                #pragma unroll
                for (int ni = 0; ni < 4; ni++)
                    mma8(acc[mi][ni], af[mi], bf[ni]);
        }
        __syncthreads();
    }

    #pragma unroll
    for (int mi = 0; mi < 4; mi++) {
        const int row = blockIdx.y * 128 + wm * 64 + mi * 16 + g;
        #pragma unroll
        for (int ni = 0; ni < 4; ni++) {
            const int col = blockIdx.x * 128 + wn * 32 + ni * 8 + 2 * q;
            *(float2*)&C[(size_t)row * N + col]       = make_float2(acc[mi][ni][0], acc[mi][ni][1]);
            *(float2*)&C[(size_t)(row + 8) * N + col] = make_float2(acc[mi][ni][2], acc[mi][ni][3]);
        }
    }
}

// ---------------------------------------------------------------------------
// RoPE in place on q,k slices (fp32). Matches jax fp32 semantics.
// ---------------------------------------------------------------------------
__global__ void rope_kernel(float* __restrict__ qkv) {
    int idx = blockIdx.x * blockDim.x + threadIdx.x;
    if (idx >= TOKENS * NH * 32) return;
    int i     = idx & 31;
    int h     = (idx >> 5) & 15;
    int token = idx >> 9;
    int s     = token & (S_LEN - 1);

    double invf_d = exp(-((double)i / 32.0) * log(10000.0));
    float  invf   = (float)invf_d;
    float  ang    = (float)s * invf;
    float  c = cosf(ang), sn = sinf(ang);

    size_t base = (size_t)token * (3 * HDIM) + h * 64;
    float q1 = qkv[base + i], q2 = qkv[base + i + 32];
    qkv[base + i]      = q1 * c - q2 * sn;
    qkv[base + i + 32] = q2 * c + q1 * sn;
    float k1 = qkv[base + HDIM + i], k2 = qkv[base + HDIM + i + 32];
    qkv[base + HDIM + i]      = k1 * c - k2 * sn;
    qkv[base + HDIM + i + 32] = k2 * c + k1 * sn;
}

// ---------------------------------------------------------------------------
// Flash attention, tf32 tensor cores, causal, base-2 softmax.
// Block = 128 q-rows of one (b,h); 8 warps, each owns 16 rows.
// Q lives in registers as tf32 A-fragments. K/V/P staged in smem (stride 68
// => fragment LDS conflict-free / 2-way worst case).
// ---------------------------------------------------------------------------
#define FS 68
__global__ void __launch_bounds__(256) flash_tf32(const float* __restrict__ qkv,
                                                  float* __restrict__ out) {
    extern __shared__ float sm[];
    float (*Ks)[FS] = (float(*)[FS])sm;                  // [64][68]  K tile [col][d]
    float (*Vs)[FS] = (float(*)[FS])(sm + 64 * FS);      // [64][68]  V tile [j][d]
    float (*Ps)[FS] = (float(*)[FS])(sm + 128 * FS);     // [128][68] P [row][j]

    const int tid  = threadIdx.x, lane = tid & 31, w = tid >> 5;
    const int g    = lane >> 2, q = lane & 3;
    const int qb   = blockIdx.x;
    const int b    = blockIdx.y >> 4, h = blockIdx.y & 15;
    const int r0   = qb * 128 + w * 16;                  // warp's first q-row

    // ---- Q fragments in registers, scaled by (1/8)*log2(e) (base-2 softmax)
    const float SC = 0.125f * 1.44269504088896340736f;
    unsigned qf[8][4];
    {
        const size_t baseLo = (size_t)(b * S_LEN + r0 + g) * 3072 + h * 64;
        const size_t baseHi = baseLo + (size_t)8 * 3072;
        #pragma unroll
        for (int kk = 0; kk < 8; kk++) {
            const int c = kk * 8 + q;
            qf[kk][0] = f2tf(qkv[baseLo + c] * SC);
            qf[kk][1] = f2tf(qkv[baseHi + c] * SC);
            qf[kk][2] = f2tf(qkv[baseLo + c + 4] * SC);
            qf[kk][3] = f2tf(qkv[baseHi + c + 4] * SC);
        }
    }

    float acc[8][4] = {};
    float m0 = -1e30f, m1 = -1e30f, l0 = 0.f, l1 = 0.f;

    const int ldR  = tid >> 2;              // 0..63
    const int ldC0 = (tid & 3) << 4;        // 0,16,32,48
    const int prL  = w * 16 + g, prH = prL + 8;
    const int jmax = 2 * qb + 1;

    for (int jb = 0; jb <= jmax; jb++) {
        // ---- load K,V 64x64 tiles (tf32-converted, vectorized stores)
        {
            const size_t kb = (size_t)(b * S_LEN + jb * 64 + ldR) * 3072 + 1024 + h * 64 + ldC0;
            #pragma unroll
            for (int i = 0; i < 4; i++) {
                float4 kv = *(const float4*)(qkv + kb + i * 4);
                float4 vv = *(const float4*)(qkv + kb + 1024 + i * 4);
                *(float4*)&Ks[ldR][ldC0 + i * 4] = make_float4(f2tff(kv.x), f2tff(kv.y), f2tff(kv.z), f2tff(kv.w));
                *(float4*)&Vs[ldR][ldC0 + i * 4] = make_float4(f2tff(vv.x), f2tff(vv.y), f2tff(vv.z), f2tff(vv.w));
            }
        }
        __syncthreads();

        if (r0 + 15 >= jb * 64) {           // warp has unmasked work in this tile
            // ---- S = Q @ K^T (in log2 domain already)
            float s[8][4] = {};
            #pragma unroll
            for (int n = 0; n < 8; n++) {
                #pragma unroll
                for (int kk = 0; kk < 8; kk++) {
                    unsigned kb2[2] = { __float_as_uint(Ks[n * 8 + g][kk * 8 + q]),
                                        __float_as_uint(Ks[n * 8 + g][kk * 8 + q + 4]) };
                    mma8(s[n], qf[kk], kb2);
                }
            }

            // ---- causal mask
            if (jb * 64 + 63 > r0) {
                #pragma unroll
                for (int n = 0; n < 8; n++) {
                    const int c0 = jb * 64 + n * 8 + 2 * q;
                    const int rL = r0 + g, rH = rL + 8;
                    if (c0 > rL)     s[n][0] = -1e30f;
                    if (c0 + 1 > rL) s[n][1] = -1e30f;
                    if (c0 > rH)     s[n][2] = -1e30f;
                    if (c0 + 1 > rH) s[n][3] = -1e30f;
                }
            }

            // ---- row max (reduce 16 regs + quad shuffle)
            float mt0 = -1e30f, mt1 = -1e30f;
            #pragma unroll
            for (int n = 0; n < 8; n++) {
                mt0 = fmaxf(mt0, fmaxf(s[n][0], s[n][1]));
                mt1 = fmaxf(mt1, fmaxf(s[n][2], s[n][3]));
            }
            mt0 = fmaxf(mt0, __shfl_xor_sync(0xffffffffu, mt0, 1));
            mt0 = fmaxf(mt0, __shfl_xor_sync(0xffffffffu, mt0, 2));
            mt1 = fmaxf(mt1, __shfl_xor_sync(0xffffffffu, mt1, 1));
            mt1 = fmaxf(mt1, __shfl_xor_sync(0xffffffffu, mt1, 2));

            const float mn0 = fmaxf(m0, mt0), mn1 = fmaxf(m1, mt1);
            const float al0 = exp2f(m0 - mn0), al1 = exp2f(m1 - mn1);

            // ---- P = 2^(s-m), row sums, store P (tf32) to smem
            float sum0 = 0.f, sum1 = 0.f;
            __syncwarp();
            #pragma unroll
            for (int n = 0; n < 8; n++) {
                float p0 = fexp2(s[n][0] - mn0), p1 = fexp2(s[n][1] - mn0);
                float p2 = fexp2(s[n][2] - mn1), p3 = fexp2(s[n][3] - mn1);
                sum0 += p0 + p1;
                sum1 += p2 + p3;
                const int c = n * 8 + 2 * q;
                *(float2*)&Ps[prL][c] = make_float2(f2tff(p0), f2tff(p1));
                *(float2*)&Ps[prH][c] = make_float2(f2tff(p2), f2tff(p3));
            }
            sum0 += __shfl_xor_sync(0xffffffffu, sum0, 1);
            sum0 += __shfl_xor_sync(0xffffffffu, sum0, 2);
            sum1 += __shfl_xor_sync(0xffffffffu, sum1, 1);
            sum1 += __shfl_xor_sync(0xffffffffu, sum1, 2);

            l0 = l0 * al0 + sum0; m0 = mn0;
            l1 = l1 * al1 + sum1; m1 = mn1;
            #pragma unroll
            for (int n = 0; n < 8; n++) {
                acc[n][0] *= al0; acc[n][1] *= al0;
                acc[n][2] *= al1; acc[n][3] *= al1;
            }
            __syncwarp();

            // ---- acc += P @ V  (A-frags hoisted over the 8 d-frags)
            #pragma unroll
            for (int kk = 0; kk < 8; kk++) {
                unsigned pa[4] = { __float_as_uint(Ps[prL][kk * 8 + q]),
                                   __float_as_uint(Ps[prH][kk * 8 + q]),
                                   __float_as_uint(Ps[prL][kk * 8 + q + 4]),
                                   __float_as_uint(Ps[prH][kk * 8 + q + 4]) };
                #pragma unroll
                for (int n = 0; n < 8; n++) {
                    unsigned vb[2] = { __float_as_uint(Vs[kk * 8 + q][n * 8 + g]),
                                       __float_as_uint(Vs[kk * 8 + q + 4][n * 8 + g]) };
                    mma8(acc[n], pa, vb);
                }
            }
            __syncwarp();
        }
        __syncthreads();
    }

    // ---- normalize + write
    const float inv0 = 1.f / l0, inv1 = 1.f / l1;
    const size_t tokLo = (size_t)(b * S_LEN + r0 + g);
    const size_t tokHi = tokLo + 8;
    #pragma unroll
    for (int n = 0; n < 8; n++) {
        const int c = h * 64 + n * 8 + 2 * q;
        *(float2*)&out[tokLo * HDIM + c] = make_float2(acc[n][0] * inv0, acc[n][1] * inv0);
        *(float2*)&out[tokHi * HDIM + c] = make_float2(acc[n][2] * inv1, acc[n][3] * inv1);
    }
}

// ---------------------------------------------------------------------------
// Launch
// ---------------------------------------------------------------------------
extern "C" void kernel_launch(void* const* d_in, const int* in_sizes, int n_in,
                              void* d_out, int out_size) {
    const float* x     = (const float*)d_in[0];
    const float* w_qkv = (const float*)d_in[1];
    const float* w_o   = (const float*)d_in[2];
    float* out = (float*)d_out;

    float *qkv, *att;
    cudaGetSymbolAddress((void**)&qkv, g_qkv);
    cudaGetSymbolAddress((void**)&att, g_att);

    // 1) QKV projection: [4096,3072] = x[4096,1024] @ w_qkv[3072,1024]^T
    gemm_tf32_nt<<<dim3(3 * HDIM / 128, TOKENS / 128), 256>>>(x, w_qkv, qkv, TOKENS, 3 * HDIM, HDIM);

    // 2) RoPE on q,k in place
    rope_kernel<<<(TOKENS * NH * 32) / 256, 256>>>(qkv);

    // 3) Causal flash attention (tf32 tensor cores)
    const int flash_smem = 256 * FS * (int)sizeof(float);  // 69632 B
    cudaFuncSetAttribute(flash_tf32, cudaFuncAttributeMaxDynamicSharedMemorySize, flash_smem);
    flash_tf32<<<dim3(S_LEN / 128, 2 * NH), 256, flash_smem>>>(qkv, att);

    // 4) Output projection: out[4096,1024] = att @ w_o[1024,1024]^T
    gemm_tf32_nt<<<dim3(HDIM / 128, TOKENS / 128), 256>>>(att, w_o, out, TOKENS, HDIM, HDIM);
}

// round 5
// speedup vs baseline: 2.8310x; 1.1259x over previous
#include <cuda_runtime.h>
#include <math.h>

#define TOKENS 4096      // B*S = 2*2048
#define S_LEN  2048
#define HDIM   1024
#define NH     16

// Scratch (static device globals — no allocations allowed)
__device__ float g_qkv[(size_t)TOKENS * 3 * HDIM];  // [token][3*1024]: q|k|v
__device__ float g_att[(size_t)TOKENS * HDIM];      // attention output

// ---------------------------------------------------------------------------
// Helpers
// ---------------------------------------------------------------------------
__device__ __forceinline__ unsigned f2tf(float x) {
    unsigned r; asm("cvt.rna.tf32.f32 %0, %1;" : "=r"(r) : "f"(x)); return r;
}
__device__ __forceinline__ float f2tff(float x) { return __uint_as_float(f2tf(x)); }

__device__ __forceinline__ void mma8(float* c, const unsigned* a, const unsigned* b) {
    asm("mma.sync.aligned.m16n8k8.row.col.f32.tf32.tf32.f32 "
        "{%0,%1,%2,%3}, {%4,%5,%6,%7}, {%8,%9}, {%0,%1,%2,%3};"
        : "+f"(c[0]), "+f"(c[1]), "+f"(c[2]), "+f"(c[3])
        : "r"(a[0]), "r"(a[1]), "r"(a[2]), "r"(a[3]), "r"(b[0]), "r"(b[1]));
}

// 2^t via round + degree-6 poly + exponent splice. No MUFU.
__device__ __forceinline__ float fexp2(float t) {
    t = fmaxf(t, -126.0f);
    float r  = __fadd_rn(t, 12582912.0f);
    int   n  = __float_as_int(r) - 0x4B400000;
    float f  = t - __fadd_rn(r, -12582912.0f);
    float p  = 1.535336188319500e-4f;
    p = fmaf(p, f, 1.339887440266574e-3f);
    p = fmaf(p, f, 9.618437357674640e-3f);
    p = fmaf(p, f, 5.550332471162809e-2f);
    p = fmaf(p, f, 2.402264791363012e-1f);
    p = fmaf(p, f, 6.931472028550421e-1f);
    p = fmaf(p, f, 1.0f);
    return p * __int_as_float((n + 127) << 23);
}

__device__ __forceinline__ void cpa16(void* s, const void* g) {
    unsigned sa = (unsigned)__cvta_generic_to_shared(s);
    asm volatile("cp.async.cg.shared.global [%0], [%1], 16;" :: "r"(sa), "l"(g));
}
__device__ __forceinline__ void cp_commit() { asm volatile("cp.async.commit_group;"); }
__device__ __forceinline__ void cp_wait0()  { asm volatile("cp.async.wait_group 0;"); }

// ---------------------------------------------------------------------------
// tf32 GEMM: C[M,N] = A[M,K] @ B[N,K]^T, row-major. 128x128 block tile,
// BK=16, 4 warps (2x2), warp tile 64x64 (1 LDS-cycle per MMA).
// Smem stride 20 -> fragment loads conflict-free.
// ---------------------------------------------------------------------------
#define GS 20
__global__ void __launch_bounds__(128, 2) gemm_tf32_nt(
        const float* __restrict__ A, const float* __restrict__ B,
        float* __restrict__ C, int M, int N, int K) {
    __shared__ float As[128][GS];
    __shared__ float Bs[128][GS];
    const int tid = threadIdx.x, lane = tid & 31;
    const int w   = tid >> 5, wm = w >> 1, wn = w & 1;
    const int g   = lane >> 2, q = lane & 3;
    const int ldR = tid >> 2, ldC = (tid & 3) << 2;   // 32 rows x 16 cols per pass

    const float* Ag = A + (size_t)(blockIdx.y * 128 + ldR) * K + ldC;
    const float* Bg = B + (size_t)(blockIdx.x * 128 + ldR) * K + ldC;

    float acc[4][8][4] = {};
    float4 ra[4], rb[4];
    #pragma unroll
    for (int j = 0; j < 4; j++) {
        ra[j] = *(const float4*)(Ag + (size_t)(32 * j) * K);
        rb[j] = *(const float4*)(Bg + (size_t)(32 * j) * K);
    }

    const int nC = K >> 4;
    for (int ch = 0; ch < nC; ch++) {
        #pragma unroll
        for (int j = 0; j < 4; j++) {
            *(float4*)&As[ldR + 32 * j][ldC] =
                make_float4(f2tff(ra[j].x), f2tff(ra[j].y), f2tff(ra[j].z), f2tff(ra[j].w));
            *(float4*)&Bs[ldR + 32 * j][ldC] =
                make_float4(f2tff(rb[j].x), f2tff(rb[j].y), f2tff(rb[j].z), f2tff(rb[j].w));
        }
        __syncthreads();

        Ag += 16; Bg += 16;
        if (ch + 1 < nC) {
            #pragma unroll
            for (int j = 0; j < 4; j++) {
                ra[j] = *(const float4*)(Ag + (size_t)(32 * j) * K);
                rb[j] = *(const float4*)(Bg + (size_t)(32 * j) * K);
            }
        }

        #pragma unroll
        for (int kk = 0; kk < 2; kk++) {
            const int cb = kk * 8 + q;
            unsigned af[4][4], bf[8][2];
            #pragma unroll
            for (int mi = 0; mi < 4; mi++) {
                const int rb2 = wm * 64 + mi * 16;
                af[mi][0] = __float_as_uint(As[rb2 + g][cb]);
                af[mi][1] = __float_as_uint(As[rb2 + 8 + g][cb]);
                af[mi][2] = __float_as_uint(As[rb2 + g][cb + 4]);
                af[mi][3] = __float_as_uint(As[rb2 + 8 + g][cb + 4]);
            }
            #pragma unroll
            for (int ni = 0; ni < 8; ni++) {
                const int nb = wn * 64 + ni * 8;
                bf[ni][0] = __float_as_uint(Bs[nb + g][cb]);
                bf[ni][1] = __float_as_uint(Bs[nb + g][cb + 4]);
            }
            #pragma unroll
            for (int mi = 0; mi < 4; mi++)
                #pragma unroll
                for (int ni = 0; ni < 8; ni++)
                    mma8(acc[mi][ni], af[mi], bf[ni]);
        }
        __syncthreads();
    }

    #pragma unroll
    for (int mi = 0; mi < 4; mi++) {
        const int row = blockIdx.y * 128 + wm * 64 + mi * 16 + g;
        #pragma unroll
        for (int ni = 0; ni < 8; ni++) {
            const int col = blockIdx.x * 128 + wn * 64 + ni * 8 + 2 * q;
            *(float2*)&C[(size_t)row * N + col]       = make_float2(acc[mi][ni][0], acc[mi][ni][1]);
            *(float2*)&C[(size_t)(row + 8) * N + col] = make_float2(acc[mi][ni][2], acc[mi][ni][3]);
        }
    }
}

// ---------------------------------------------------------------------------
// RoPE in place on q,k (fp32 math, matches jax), then rna-round k AND v to
// tf32 so flash can cp.async raw bytes with round-3 numerics.
// ---------------------------------------------------------------------------
__global__ void rope_kernel(float* __restrict__ qkv) {
    int idx = blockIdx.x * blockDim.x + threadIdx.x;
    if (idx >= TOKENS * NH * 32) return;
    int i     = idx & 31;
    int h     = (idx >> 5) & 15;
    int token = idx >> 9;
    int s     = token & (S_LEN - 1);

    double invf_d = exp(-((double)i / 32.0) * log(10000.0));
    float  invf   = (float)invf_d;
    float  ang    = (float)s * invf;
    float  c = cosf(ang), sn = sinf(ang);

    size_t base = (size_t)token * (3 * HDIM) + h * 64;
    float q1 = qkv[base + i], q2 = qkv[base + i + 32];
    qkv[base + i]      = q1 * c - q2 * sn;
    qkv[base + i + 32] = q2 * c + q1 * sn;
    float k1 = qkv[base + HDIM + i], k2 = qkv[base + HDIM + i + 32];
    qkv[base + HDIM + i]      = f2tff(k1 * c - k2 * sn);
    qkv[base + HDIM + i + 32] = f2tff(k2 * c + k1 * sn);
    qkv[base + 2 * HDIM + i]      = f2tff(qkv[base + 2 * HDIM + i]);
    qkv[base + 2 * HDIM + i + 32] = f2tff(qkv[base + 2 * HDIM + i + 32]);
}

// ---------------------------------------------------------------------------
// Flash attention, tf32 mma, causal, base-2 softmax.
// Block = 128 q-rows of one (b,h); 4 warps x 32 rows (mi=2).
// Q fragments in registers. K/V double-buffered via cp.async (1 bar/tile).
// P never touches smem: S C-frags -> PV A-frags via register shuffles.
// ---------------------------------------------------------------------------
#define FS 68
__global__ void __launch_bounds__(128, 2) flash_tf32(const float* __restrict__ qkv,
                                                     float* __restrict__ out) {
    extern __shared__ float sm[];
    float (*Ks)[64][FS] = (float(*)[64][FS])sm;                    // [2][64][68]
    float (*Vs)[64][FS] = (float(*)[64][FS])(sm + 2 * 64 * FS);    // [2][64][68]

    const int tid = threadIdx.x, lane = tid & 31, w = tid >> 5;
    const int g   = lane >> 2, q = lane & 3;
    const int qb  = gridDim.x - 1 - blockIdx.x;          // heavy blocks first
    const int b   = blockIdx.y >> 4, h = blockIdx.y & 15;
    const int r0  = qb * 128 + w * 32;                   // warp's first q-row

    // ---- Q fragments in registers, scaled by (1/8)*log2(e)
    const float SC = 0.125f * 1.44269504088896340736f;
    unsigned qf[2][8][4];
    #pragma unroll
    for (int mi = 0; mi < 2; mi++) {
        const size_t bl = (size_t)(b * S_LEN + r0 + mi * 16 + g) * 3072 + h * 64;
        const size_t bh = bl + (size_t)8 * 3072;
        #pragma unroll
        for (int kk = 0; kk < 8; kk++) {
            const int c = kk * 8 + q;
            qf[mi][kk][0] = f2tf(qkv[bl + c] * SC);
            qf[mi][kk][1] = f2tf(qkv[bh + c] * SC);
            qf[mi][kk][2] = f2tf(qkv[bl + c + 4] * SC);
            qf[mi][kk][3] = f2tf(qkv[bh + c + 4] * SC);
        }
    }

    float acc[2][8][4] = {};
    float m_[2][2], l_[2][2];
    #pragma unroll
    for (int mi = 0; mi < 2; mi++) { m_[mi][0] = m_[mi][1] = -1e30f; l_[mi][0] = l_[mi][1] = 0.f; }

    const int ldR = tid >> 1, ldC = (tid & 1) * 32;      // cp.async mapping
    const int jmax = 2 * qb + 1;

    // prefetch tile 0
    {
        const size_t gb = (size_t)(b * S_LEN + ldR) * 3072 + 1024 + h * 64 + ldC;
        #pragma unroll
        for (int i = 0; i < 8; i++) cpa16(&Ks[0][ldR][ldC + 4 * i], qkv + gb + 4 * i);
        #pragma unroll
        for (int i = 0; i < 8; i++) cpa16(&Vs[0][ldR][ldC + 4 * i], qkv + gb + 1024 + 4 * i);
    }
    cp_commit();

    for (int jb = 0; jb <= jmax; jb++) {
        cp_wait0();
        __syncthreads();

        if (jb < jmax) {   // prefetch next tile into the other buffer
            const int nb = (jb + 1) & 1;
            const size_t gb = (size_t)(b * S_LEN + (jb + 1) * 64 + ldR) * 3072 + 1024 + h * 64 + ldC;
            #pragma unroll
            for (int i = 0; i < 8; i++) cpa16(&Ks[nb][ldR][ldC + 4 * i], qkv + gb + 4 * i);
            #pragma unroll
            for (int i = 0; i < 8; i++) cpa16(&Vs[nb][ldR][ldC + 4 * i], qkv + gb + 1024 + 4 * i);
            cp_commit();
        }

        if (r0 + 31 >= jb * 64) {                        // warp has unmasked work
            const float (*K)[FS] = Ks[jb & 1];
            const float (*V)[FS] = Vs[jb & 1];

            // ---- S = Q @ K^T  (K-frag reused across mi)
            float p[2][8][4];
            #pragma unroll
            for (int n = 0; n < 8; n++) {
                float s0[4] = {}, s1[4] = {};
                #pragma unroll
                for (int kk = 0; kk < 8; kk++) {
                    unsigned kb2[2] = { __float_as_uint(K[n * 8 + g][kk * 8 + q]),
                                        __float_as_uint(K[n * 8 + g][kk * 8 + q + 4]) };
                    mma8(s0, qf[0][kk], kb2);
                    mma8(s1, qf[1][kk], kb2);
                }
                #pragma unroll
                for (int e = 0; e < 4; e++) { p[0][n][e] = s0[e]; p[1][n][e] = s1[e]; }
            }

            // ---- causal mask (diagonal region only)
            if (jb * 64 + 63 > r0) {
                #pragma unroll
                for (int mi = 0; mi < 2; mi++) {
                    const int rL = r0 + mi * 16 + g, rH = rL + 8;
                    #pragma unroll
                    for (int n = 0; n < 8; n++) {
                        const int c0 = jb * 64 + n * 8 + 2 * q;
                        if (c0 > rL)     p[mi][n][0] = -1e30f;
                        if (c0 + 1 > rL) p[mi][n][1] = -1e30f;
                        if (c0 > rH)     p[mi][n][2] = -1e30f;
                        if (c0 + 1 > rH) p[mi][n][3] = -1e30f;
                    }
                }
            }

            // ---- online softmax (base 2); p -> tf32 in place
            #pragma unroll
            for (int mi = 0; mi < 2; mi++) {
                float mt0 = -1e30f, mt1 = -1e30f;
                #pragma unroll
                for (int n = 0; n < 8; n++) {
                    mt0 = fmaxf(mt0, fmaxf(p[mi][n][0], p[mi][n][1]));
                    mt1 = fmaxf(mt1, fmaxf(p[mi][n][2], p[mi][n][3]));
                }
                mt0 = fmaxf(mt0, __shfl_xor_sync(0xffffffffu, mt0, 1));
                mt0 = fmaxf(mt0, __shfl_xor_sync(0xffffffffu, mt0, 2));
                mt1 = fmaxf(mt1, __shfl_xor_sync(0xffffffffu, mt1, 1));
                mt1 = fmaxf(mt1, __shfl_xor_sync(0xffffffffu, mt1, 2));

                const float mn0 = fmaxf(m_[mi][0], mt0), mn1 = fmaxf(m_[mi][1], mt1);
                const float al0 = exp2f(m_[mi][0] - mn0), al1 = exp2f(m_[mi][1] - mn1);

                float sum0 = 0.f, sum1 = 0.f;
                #pragma unroll
                for (int n = 0; n < 8; n++) {
                    float p0 = fexp2(p[mi][n][0] - mn0), p1 = fexp2(p[mi][n][1] - mn0);
                    float p2 = fexp2(p[mi][n][2] - mn1), p3 = fexp2(p[mi][n][3] - mn1);
                    sum0 += p0 + p1; sum1 += p2 + p3;
                    p[mi][n][0] = f2tff(p0); p[mi][n][1] = f2tff(p1);
                    p[mi][n][2] = f2tff(p2); p[mi][n][3] = f2tff(p3);
                }
                sum0 += __shfl_xor_sync(0xffffffffu, sum0, 1);
                sum0 += __shfl_xor_sync(0xffffffffu, sum0, 2);
                sum1 += __shfl_xor_sync(0xffffffffu, sum1, 1);
                sum1 += __shfl_xor_sync(0xffffffffu, sum1, 2);

                l_[mi][0] = l_[mi][0] * al0 + sum0; m_[mi][0] = mn0;
                l_[mi][1] = l_[mi][1] * al1 + sum1; m_[mi][1] = mn1;
                #pragma unroll
                for (int n = 0; n < 8; n++) {
                    acc[mi][n][0] *= al0; acc[mi][n][1] *= al0;
                    acc[mi][n][2] *= al1; acc[mi][n][3] *= al1;
                }
            }

            // ---- acc += P @ V ; P A-frags built from C-frags via shuffles
            const int s1l = (lane & ~3) | (q >> 1);
            const int s2l = s1l + 2;
            const bool eo = (q & 1) != 0;
            #pragma unroll
            for (int kk = 0; kk < 8; kk++) {
                unsigned pa[2][4];
                #pragma unroll
                for (int mi = 0; mi < 2; mi++) {
                    float t0 = __shfl_sync(0xffffffffu, p[mi][kk][0], s1l);
                    float t1 = __shfl_sync(0xffffffffu, p[mi][kk][1], s1l);
                    float t2 = __shfl_sync(0xffffffffu, p[mi][kk][0], s2l);
                    float t3 = __shfl_sync(0xffffffffu, p[mi][kk][1], s2l);
                    float u0 = __shfl_sync(0xffffffffu, p[mi][kk][2], s1l);
                    float u1 = __shfl_sync(0xffffffffu, p[mi][kk][3], s1l);
                    float u2 = __shfl_sync(0xffffffffu, p[mi][kk][2], s2l);
                    float u3 = __shfl_sync(0xffffffffu, p[mi][kk][3], s2l);
                    pa[mi][0] = __float_as_uint(eo ? t1 : t0);   // (row g,   col q)
                    pa[mi][1] = __float_as_uint(eo ? u1 : u0);   // (row g+8, col q)
                    pa[mi][2] = __float_as_uint(eo ? t3 : t2);   // (row g,   col q+4)
                    pa[mi][3] = __float_as_uint(eo ? u3 : u2);   // (row g+8, col q+4)
                }
                #pragma unroll
                for (int n = 0; n < 8; n++) {
                    unsigned vb[2] = { __float_as_uint(V[kk * 8 + q][n * 8 + g]),
                                       __float_as_uint(V[kk * 8 + q + 4][n * 8 + g]) };
                    mma8(acc[0][n], pa[0], vb);
                    mma8(acc[1][n], pa[1], vb);
                }
            }
        }
    }

    // ---- normalize + write
    #pragma unroll
    for (int mi = 0; mi < 2; mi++) {
        const float inv0 = 1.f / l_[mi][0], inv1 = 1.f / l_[mi][1];
        const size_t tokL = (size_t)(b * S_LEN + r0 + mi * 16 + g);
        const size_t tokH = tokL + 8;
        #pragma unroll
        for (int n = 0; n < 8; n++) {
            const int c = h * 64 + n * 8 + 2 * q;
            *(float2*)&out[tokL * HDIM + c] = make_float2(acc[mi][n][0] * inv0, acc[mi][n][1] * inv0);
            *(float2*)&out[tokH * HDIM + c] = make_float2(acc[mi][n][2] * inv1, acc[mi][n][3] * inv1);
        }
    }
}

// ---------------------------------------------------------------------------
// Launch
// ---------------------------------------------------------------------------
extern "C" void kernel_launch(void* const* d_in, const int* in_sizes, int n_in,
                              void* d_out, int out_size) {
    const float* x     = (const float*)d_in[0];
    const float* w_qkv = (const float*)d_in[1];
    const float* w_o   = (const float*)d_in[2];
    float* out = (float*)d_out;

    float *qkv, *att;
    cudaGetSymbolAddress((void**)&qkv, g_qkv);
    cudaGetSymbolAddress((void**)&att, g_att);

    // 1) QKV projection: [4096,3072] = x[4096,1024] @ w_qkv[3072,1024]^T
    gemm_tf32_nt<<<dim3(3 * HDIM / 128, TOKENS / 128), 128>>>(x, w_qkv, qkv, TOKENS, 3 * HDIM, HDIM);

    // 2) RoPE on q,k in place (+ tf32 rounding of k,v)
    rope_kernel<<<(TOKENS * NH * 32) / 256, 256>>>(qkv);

    // 3) Causal flash attention (tf32 tensor cores, cp.async pipeline)
    const int flash_smem = 4 * 64 * FS * (int)sizeof(float);  // 69632 B
    cudaFuncSetAttribute(flash_tf32, cudaFuncAttributeMaxDynamicSharedMemorySize, flash_smem);
    flash_tf32<<<dim3(S_LEN / 128, 2 * NH), 128, flash_smem>>>(qkv, att);

    // 4) Output projection: out[4096,1024] = att @ w_o[1024,1024]^T
    gemm_tf32_nt<<<dim3(HDIM / 128, TOKENS / 128), 128>>>(att, w_o, out, TOKENS, HDIM, HDIM);
}

// round 6
// speedup vs baseline: 2.8377x; 1.0024x over previous
#include <cuda_runtime.h>
#include <math.h>

#define TOKENS 4096      // B*S = 2*2048
#define S_LEN  2048
#define HDIM   1024
#define NH     16

// Scratch (static device globals — no allocations allowed)
__device__ float g_qkv[(size_t)TOKENS * 3 * HDIM];  // [token][3*1024]: q|k|v
__device__ float g_att[(size_t)TOKENS * HDIM];      // attention output

// ---------------------------------------------------------------------------
// Helpers
// ---------------------------------------------------------------------------
__device__ __forceinline__ unsigned f2tf(float x) {
    unsigned r; asm("cvt.rna.tf32.f32 %0, %1;" : "=r"(r) : "f"(x)); return r;
}
__device__ __forceinline__ float f2tff(float x) { return __uint_as_float(f2tf(x)); }

__device__ __forceinline__ void mma8(float* c, const unsigned* a, const unsigned* b) {
    asm("mma.sync.aligned.m16n8k8.row.col.f32.tf32.tf32.f32 "
        "{%0,%1,%2,%3}, {%4,%5,%6,%7}, {%8,%9}, {%0,%1,%2,%3};"
        : "+f"(c[0]), "+f"(c[1]), "+f"(c[2]), "+f"(c[3])
        : "r"(a[0]), "r"(a[1]), "r"(a[2]), "r"(a[3]), "r"(b[0]), "r"(b[1]));
}

// 2^t via round + degree-6 poly + exponent splice. No MUFU.
__device__ __forceinline__ float fexp2(float t) {
    t = fmaxf(t, -126.0f);
    float r  = __fadd_rn(t, 12582912.0f);
    int   n  = __float_as_int(r) - 0x4B400000;
    float f  = t - __fadd_rn(r, -12582912.0f);
    float p  = 1.535336188319500e-4f;
    p = fmaf(p, f, 1.339887440266574e-3f);
    p = fmaf(p, f, 9.618437357674640e-3f);
    p = fmaf(p, f, 5.550332471162809e-2f);
    p = fmaf(p, f, 2.402264791363012e-1f);
    p = fmaf(p, f, 6.931472028550421e-1f);
    p = fmaf(p, f, 1.0f);
    return p * __int_as_float((n + 127) << 23);
}

__device__ __forceinline__ void cpa16(void* s, const void* g) {
    unsigned sa = (unsigned)__cvta_generic_to_shared(s);
    asm volatile("cp.async.cg.shared.global [%0], [%1], 16;" :: "r"(sa), "l"(g));
}
__device__ __forceinline__ void cp_commit() { asm volatile("cp.async.commit_group;"); }
__device__ __forceinline__ void cp_wait0()  { asm volatile("cp.async.wait_group 0;"); }

// ---------------------------------------------------------------------------
// tf32 GEMM: C[M,N] = A[M,K] @ B[N,K]^T, row-major. 128x128 block tile,
// BK=16, 4 warps (2x2), warp tile 64x64 (1 LDS-cycle per MMA).
// Smem stride 20 -> fragment loads conflict-free.
// ---------------------------------------------------------------------------
#define GS 20
__global__ void __launch_bounds__(128, 2) gemm_tf32_nt(
        const float* __restrict__ A, const float* __restrict__ B,
        float* __restrict__ C, int M, int N, int K) {
    __shared__ float As[128][GS];
    __shared__ float Bs[128][GS];
    const int tid = threadIdx.x, lane = tid & 31;
    const int w   = tid >> 5, wm = w >> 1, wn = w & 1;
    const int g   = lane >> 2, q = lane & 3;
    const int ldR = tid >> 2, ldC = (tid & 3) << 2;   // 32 rows x 16 cols per pass

    const float* Ag = A + (size_t)(blockIdx.y * 128 + ldR) * K + ldC;
    const float* Bg = B + (size_t)(blockIdx.x * 128 + ldR) * K + ldC;

    float acc[4][8][4] = {};
    float4 ra[4], rb[4];
    #pragma unroll
    for (int j = 0; j < 4; j++) {
        ra[j] = *(const float4*)(Ag + (size_t)(32 * j) * K);
        rb[j] = *(const float4*)(Bg + (size_t)(32 * j) * K);
    }

    const int nC = K >> 4;
    for (int ch = 0; ch < nC; ch++) {
        #pragma unroll
        for (int j = 0; j < 4; j++) {
            *(float4*)&As[ldR + 32 * j][ldC] =
                make_float4(f2tff(ra[j].x), f2tff(ra[j].y), f2tff(ra[j].z), f2tff(ra[j].w));
            *(float4*)&Bs[ldR + 32 * j][ldC] =
                make_float4(f2tff(rb[j].x), f2tff(rb[j].y), f2tff(rb[j].z), f2tff(rb[j].w));
        }
        __syncthreads();

        Ag += 16; Bg += 16;
        if (ch + 1 < nC) {
            #pragma unroll
            for (int j = 0; j < 4; j++) {
                ra[j] = *(const float4*)(Ag + (size_t)(32 * j) * K);
                rb[j] = *(const float4*)(Bg + (size_t)(32 * j) * K);
            }
        }

        #pragma unroll
        for (int kk = 0; kk < 2; kk++) {
            const int cb = kk * 8 + q;
            unsigned af[4][4], bf[8][2];
            #pragma unroll
            for (int mi = 0; mi < 4; mi++) {
                const int rb2 = wm * 64 + mi * 16;
                af[mi][0] = __float_as_uint(As[rb2 + g][cb]);
                af[mi][1] = __float_as_uint(As[rb2 + 8 + g][cb]);
                af[mi][2] = __float_as_uint(As[rb2 + g][cb + 4]);
                af[mi][3] = __float_as_uint(As[rb2 + 8 + g][cb + 4]);
            }
            #pragma unroll
            for (int ni = 0; ni < 8; ni++) {
                const int nb = wn * 64 + ni * 8;
                bf[ni][0] = __float_as_uint(Bs[nb + g][cb]);
                bf[ni][1] = __float_as_uint(Bs[nb + g][cb + 4]);
            }
            #pragma unroll
            for (int mi = 0; mi < 4; mi++)
                #pragma unroll
                for (int ni = 0; ni < 8; ni++)
                    mma8(acc[mi][ni], af[mi], bf[ni]);
        }
        __syncthreads();
    }

    #pragma unroll
    for (int mi = 0; mi < 4; mi++) {
        const int row = blockIdx.y * 128 + wm * 64 + mi * 16 + g;
        #pragma unroll
        for (int ni = 0; ni < 8; ni++) {
            const int col = blockIdx.x * 128 + wn * 64 + ni * 8 + 2 * q;
            *(float2*)&C[(size_t)row * N + col]       = make_float2(acc[mi][ni][0], acc[mi][ni][1]);
            *(float2*)&C[(size_t)(row + 8) * N + col] = make_float2(acc[mi][ni][2], acc[mi][ni][3]);
        }
    }
}

// ---------------------------------------------------------------------------
// RoPE in place on q,k (fp32 math, matches jax), then rna-round k AND v to
// tf32 so flash can cp.async raw bytes with round-3 numerics.
// ---------------------------------------------------------------------------
__global__ void rope_kernel(float* __restrict__ qkv) {
    int idx = blockIdx.x * blockDim.x + threadIdx.x;
    if (idx >= TOKENS * NH * 32) return;
    int i     = idx & 31;
    int h     = (idx >> 5) & 15;
    int token = idx >> 9;
    int s     = token & (S_LEN - 1);

    double invf_d = exp(-((double)i / 32.0) * log(10000.0));
    float  invf   = (float)invf_d;
    float  ang    = (float)s * invf;
    float  c = cosf(ang), sn = sinf(ang);

    size_t base = (size_t)token * (3 * HDIM) + h * 64;
    float q1 = qkv[base + i], q2 = qkv[base + i + 32];
    qkv[base + i]      = q1 * c - q2 * sn;
    qkv[base + i + 32] = q2 * c + q1 * sn;
    float k1 = qkv[base + HDIM + i], k2 = qkv[base + HDIM + i + 32];
    qkv[base + HDIM + i]      = f2tff(k1 * c - k2 * sn);
    qkv[base + HDIM + i + 32] = f2tff(k2 * c + k1 * sn);
    qkv[base + 2 * HDIM + i]      = f2tff(qkv[base + 2 * HDIM + i]);
    qkv[base + 2 * HDIM + i + 32] = f2tff(qkv[base + 2 * HDIM + i + 32]);
}

// ---------------------------------------------------------------------------
// Flash attention, tf32 mma, causal, base-2 softmax.
// Block = 128 q-rows of one (b,h); 4 warps x 32 rows (mi=2).
// Q fragments in registers. K/V double-buffered via cp.async (1 bar/tile).
// P never touches smem: S C-frags -> PV A-frags via register shuffles.
// ---------------------------------------------------------------------------
#define FS 68
__global__ void __launch_bounds__(128, 2) flash_tf32(const float* __restrict__ qkv,
                                                     float* __restrict__ out) {
    extern __shared__ float sm[];
    float (*Ks)[64][FS] = (float(*)[64][FS])sm;                    // [2][64][68]
    float (*Vs)[64][FS] = (float(*)[64][FS])(sm + 2 * 64 * FS);    // [2][64][68]

    const int tid = threadIdx.x, lane = tid & 31, w = tid >> 5;
    const int g   = lane >> 2, q = lane & 3;
    const int qb  = gridDim.x - 1 - blockIdx.x;          // heavy blocks first
    const int b   = blockIdx.y >> 4, h = blockIdx.y & 15;
    const int r0  = qb * 128 + w * 32;                   // warp's first q-row

    // ---- Q fragments in registers, scaled by (1/8)*log2(e)
    const float SC = 0.125f * 1.44269504088896340736f;
    unsigned qf[2][8][4];
    #pragma unroll
    for (int mi = 0; mi < 2; mi++) {
        const size_t bl = (size_t)(b * S_LEN + r0 + mi * 16 + g) * 3072 + h * 64;
        const size_t bh = bl + (size_t)8 * 3072;
        #pragma unroll
        for (int kk = 0; kk < 8; kk++) {
            const int c = kk * 8 + q;
            qf[mi][kk][0] = f2tf(qkv[bl + c] * SC);
            qf[mi][kk][1] = f2tf(qkv[bh + c] * SC);
            qf[mi][kk][2] = f2tf(qkv[bl + c + 4] * SC);
            qf[mi][kk][3] = f2tf(qkv[bh + c + 4] * SC);
        }
    }

    float acc[2][8][4] = {};
    float m_[2][2], l_[2][2];
    #pragma unroll
    for (int mi = 0; mi < 2; mi++) { m_[mi][0] = m_[mi][1] = -1e30f; l_[mi][0] = l_[mi][1] = 0.f; }

    const int ldR = tid >> 1, ldC = (tid & 1) * 32;      // cp.async mapping
    const int jmax = 2 * qb + 1;

    // prefetch tile 0
    {
        const size_t gb = (size_t)(b * S_LEN + ldR) * 3072 + 1024 + h * 64 + ldC;
        #pragma unroll
        for (int i = 0; i < 8; i++) cpa16(&Ks[0][ldR][ldC + 4 * i], qkv + gb + 4 * i);
        #pragma unroll
        for (int i = 0; i < 8; i++) cpa16(&Vs[0][ldR][ldC + 4 * i], qkv + gb + 1024 + 4 * i);
    }
    cp_commit();

    for (int jb = 0; jb <= jmax; jb++) {
        cp_wait0();
        __syncthreads();

        if (jb < jmax) {   // prefetch next tile into the other buffer
            const int nb = (jb + 1) & 1;
            const size_t gb = (size_t)(b * S_LEN + (jb + 1) * 64 + ldR) * 3072 + 1024 + h * 64 + ldC;
            #pragma unroll
            for (int i = 0; i < 8; i++) cpa16(&Ks[nb][ldR][ldC + 4 * i], qkv + gb + 4 * i);
            #pragma unroll
            for (int i = 0; i < 8; i++) cpa16(&Vs[nb][ldR][ldC + 4 * i], qkv + gb + 1024 + 4 * i);
            cp_commit();
        }

        if (r0 + 31 >= jb * 64) {                        // warp has unmasked work
            const float (*K)[FS] = Ks[jb & 1];
            const float (*V)[FS] = Vs[jb & 1];

            // ---- S = Q @ K^T  (K-frag reused across mi)
            float p[2][8][4];
            #pragma unroll
            for (int n = 0; n < 8; n++) {
                float s0[4] = {}, s1[4] = {};
                #pragma unroll
                for (int kk = 0; kk < 8; kk++) {
                    unsigned kb2[2] = { __float_as_uint(K[n * 8 + g][kk * 8 + q]),
                                        __float_as_uint(K[n * 8 + g][kk * 8 + q + 4]) };
                    mma8(s0, qf[0][kk], kb2);
                    mma8(s1, qf[1][kk], kb2);
                }
                #pragma unroll
                for (int e = 0; e < 4; e++) { p[0][n][e] = s0[e]; p[1][n][e] = s1[e]; }
            }

            // ---- causal mask (diagonal region only)
            if (jb * 64 + 63 > r0) {
                #pragma unroll
                for (int mi = 0; mi < 2; mi++) {
                    const int rL = r0 + mi * 16 + g, rH = rL + 8;
                    #pragma unroll
                    for (int n = 0; n < 8; n++) {
                        const int c0 = jb * 64 + n * 8 + 2 * q;
                        if (c0 > rL)     p[mi][n][0] = -1e30f;
                        if (c0 + 1 > rL) p[mi][n][1] = -1e30f;
                        if (c0 > rH)     p[mi][n][2] = -1e30f;
                        if (c0 + 1 > rH) p[mi][n][3] = -1e30f;
                    }
                }
            }

            // ---- online softmax (base 2); p -> tf32 in place
            #pragma unroll
            for (int mi = 0; mi < 2; mi++) {
                float mt0 = -1e30f, mt1 = -1e30f;
                #pragma unroll
                for (int n = 0; n < 8; n++) {
                    mt0 = fmaxf(mt0, fmaxf(p[mi][n][0], p[mi][n][1]));
                    mt1 = fmaxf(mt1, fmaxf(p[mi][n][2], p[mi][n][3]));
                }
                mt0 = fmaxf(mt0, __shfl_xor_sync(0xffffffffu, mt0, 1));
                mt0 = fmaxf(mt0, __shfl_xor_sync(0xffffffffu, mt0, 2));
                mt1 = fmaxf(mt1, __shfl_xor_sync(0xffffffffu, mt1, 1));
                mt1 = fmaxf(mt1, __shfl_xor_sync(0xffffffffu, mt1, 2));

                const float mn0 = fmaxf(m_[mi][0], mt0), mn1 = fmaxf(m_[mi][1], mt1);
                const float al0 = exp2f(m_[mi][0] - mn0), al1 = exp2f(m_[mi][1] - mn1);

                float sum0 = 0.f, sum1 = 0.f;
                #pragma unroll
                for (int n = 0; n < 8; n++) {
                    float p0 = fexp2(p[mi][n][0] - mn0), p1 = fexp2(p[mi][n][1] - mn0);
                    float p2 = fexp2(p[mi][n][2] - mn1), p3 = fexp2(p[mi][n][3] - mn1);
                    sum0 += p0 + p1; sum1 += p2 + p3;
                    p[mi][n][0] = f2tff(p0); p[mi][n][1] = f2tff(p1);
                    p[mi][n][2] = f2tff(p2); p[mi][n][3] = f2tff(p3);
                }
                sum0 += __shfl_xor_sync(0xffffffffu, sum0, 1);
                sum0 += __shfl_xor_sync(0xffffffffu, sum0, 2);
                sum1 += __shfl_xor_sync(0xffffffffu, sum1, 1);
                sum1 += __shfl_xor_sync(0xffffffffu, sum1, 2);

                l_[mi][0] = l_[mi][0] * al0 + sum0; m_[mi][0] = mn0;
                l_[mi][1] = l_[mi][1] * al1 + sum1; m_[mi][1] = mn1;
                #pragma unroll
                for (int n = 0; n < 8; n++) {
                    acc[mi][n][0] *= al0; acc[mi][n][1] *= al0;
                    acc[mi][n][2] *= al1; acc[mi][n][3] *= al1;
                }
            }

            // ---- acc += P @ V ; P A-frags built from C-frags via shuffles
            const int s1l = (lane & ~3) | (q >> 1);
            const int s2l = s1l + 2;
            const bool eo = (q & 1) != 0;
            #pragma unroll
            for (int kk = 0; kk < 8; kk++) {
                unsigned pa[2][4];
                #pragma unroll
                for (int mi = 0; mi < 2; mi++) {
                    float t0 = __shfl_sync(0xffffffffu, p[mi][kk][0], s1l);
                    float t1 = __shfl_sync(0xffffffffu, p[mi][kk][1], s1l);
                    float t2 = __shfl_sync(0xffffffffu, p[mi][kk][0], s2l);
                    float t3 = __shfl_sync(0xffffffffu, p[mi][kk][1], s2l);
                    float u0 = __shfl_sync(0xffffffffu, p[mi][kk][2], s1l);
                    float u1 = __shfl_sync(0xffffffffu, p[mi][kk][3], s1l);
                    float u2 = __shfl_sync(0xffffffffu, p[mi][kk][2], s2l);
                    float u3 = __shfl_sync(0xffffffffu, p[mi][kk][3], s2l);
                    pa[mi][0] = __float_as_uint(eo ? t1 : t0);   // (row g,   col q)
                    pa[mi][1] = __float_as_uint(eo ? u1 : u0);   // (row g+8, col q)
                    pa[mi][2] = __float_as_uint(eo ? t3 : t2);   // (row g,   col q+4)
                    pa[mi][3] = __float_as_uint(eo ? u3 : u2);   // (row g+8, col q+4)
                }
                #pragma unroll
                for (int n = 0; n < 8; n++) {
                    unsigned vb[2] = { __float_as_uint(V[kk * 8 + q][n * 8 + g]),
                                       __float_as_uint(V[kk * 8 + q + 4][n * 8 + g]) };
                    mma8(acc[0][n], pa[0], vb);
                    mma8(acc[1][n], pa[1], vb);
                }
            }
        }
    }

    // ---- normalize + write
    #pragma unroll
    for (int mi = 0; mi < 2; mi++) {
        const float inv0 = 1.f / l_[mi][0], inv1 = 1.f / l_[mi][1];
        const size_t tokL = (size_t)(b * S_LEN + r0 + mi * 16 + g);
        const size_t tokH = tokL + 8;
        #pragma unroll
        for (int n = 0; n < 8; n++) {
            const int c = h * 64 + n * 8 + 2 * q;
            *(float2*)&out[tokL * HDIM + c] = make_float2(acc[mi][n][0] * inv0, acc[mi][n][1] * inv0);
            *(float2*)&out[tokH * HDIM + c] = make_float2(acc[mi][n][2] * inv1, acc[mi][n][3] * inv1);
        }
    }
}

// ---------------------------------------------------------------------------
// Launch
// ---------------------------------------------------------------------------
extern "C" void kernel_launch(void* const* d_in, const int* in_sizes, int n_in,
                              void* d_out, int out_size) {
    const float* x     = (const float*)d_in[0];
    const float* w_qkv = (const float*)d_in[1];
    const float* w_o   = (const float*)d_in[2];
    float* out = (float*)d_out;

    float *qkv, *att;
    cudaGetSymbolAddress((void**)&qkv, g_qkv);
    cudaGetSymbolAddress((void**)&att, g_att);

    // 1) QKV projection: [4096,3072] = x[4096,1024] @ w_qkv[3072,1024]^T
    gemm_tf32_nt<<<dim3(3 * HDIM / 128, TOKENS / 128), 128>>>(x, w_qkv, qkv, TOKENS, 3 * HDIM, HDIM);

    // 2) RoPE on q,k in place (+ tf32 rounding of k,v)
    rope_kernel<<<(TOKENS * NH * 32) / 256, 256>>>(qkv);

    // 3) Causal flash attention (tf32 tensor cores, cp.async pipeline)
    const int flash_smem = 4 * 64 * FS * (int)sizeof(float);  // 69632 B
    cudaFuncSetAttribute(flash_tf32, cudaFuncAttributeMaxDynamicSharedMemorySize, flash_smem);
    flash_tf32<<<dim3(S_LEN / 128, 2 * NH), 128, flash_smem>>>(qkv, att);

    // 4) Output projection: out[4096,1024] = att @ w_o[1024,1024]^T
    gemm_tf32_nt<<<dim3(HDIM / 128, TOKENS / 128), 128>>>(att, w_o, out, TOKENS, HDIM, HDIM);
}

// round 7
// speedup vs baseline: 3.2531x; 1.1464x over previous
#include <cuda_runtime.h>
#include <cuda_fp16.h>
#include <math.h>

#define TOKENS 4096      // B*S = 2*2048
#define S_LEN  2048
#define HDIM   1024
#define NH     16

// Scratch (static device globals — no allocations allowed)
__device__ __align__(256) float g_qkv[(size_t)TOKENS * 3 * HDIM]; // [token][3*1024]
__device__ __align__(256) float g_att[(size_t)TOKENS * HDIM];
__device__ __align__(256) float g_kf [(size_t)32 * S_LEN * 64];   // K frag-ordered [bh][s][64]
__device__ __align__(256) __half g_vph[(size_t)32 * 1024 * 64 * 2]; // V half2 pairs [bh][s/2][64]

// ---------------------------------------------------------------------------
// Helpers
// ---------------------------------------------------------------------------
__device__ __forceinline__ unsigned f2tf(float x) {
    unsigned r; asm("cvt.rna.tf32.f32 %0, %1;" : "=r"(r) : "f"(x)); return r;
}
__device__ __forceinline__ float f2tff(float x) { return __uint_as_float(f2tf(x)); }

__device__ __forceinline__ void mma8(float* c, const unsigned* a, const unsigned* b) {
    asm("mma.sync.aligned.m16n8k8.row.col.f32.tf32.tf32.f32 "
        "{%0,%1,%2,%3}, {%4,%5,%6,%7}, {%8,%9}, {%0,%1,%2,%3};"
        : "+f"(c[0]), "+f"(c[1]), "+f"(c[2]), "+f"(c[3])
        : "r"(a[0]), "r"(a[1]), "r"(a[2]), "r"(a[3]), "r"(b[0]), "r"(b[1]));
}
__device__ __forceinline__ void hmma16(float* c, const unsigned* a, const unsigned* b) {
    asm("mma.sync.aligned.m16n8k16.row.col.f32.f16.f16.f32 "
        "{%0,%1,%2,%3}, {%4,%5,%6,%7}, {%8,%9}, {%0,%1,%2,%3};"
        : "+f"(c[0]), "+f"(c[1]), "+f"(c[2]), "+f"(c[3])
        : "r"(a[0]), "r"(a[1]), "r"(a[2]), "r"(a[3]), "r"(b[0]), "r"(b[1]));
}
// pack {lo=lo, hi=hi} fp16x2
__device__ __forceinline__ unsigned pkh2(float hi, float lo) {
    unsigned d; asm("cvt.rn.f16x2.f32 %0, %1, %2;" : "=r"(d) : "f"(hi), "f"(lo)); return d;
}

// 2^t: round + degree-6 poly + exponent splice. No MUFU.
__device__ __forceinline__ float fexp2(float t) {
    t = fmaxf(t, -126.0f);
    float r  = __fadd_rn(t, 12582912.0f);
    int   n  = __float_as_int(r) - 0x4B400000;
    float f  = t - __fadd_rn(r, -12582912.0f);
    float p  = 1.535336188319500e-4f;
    p = fmaf(p, f, 1.339887440266574e-3f);
    p = fmaf(p, f, 9.618437357674640e-3f);
    p = fmaf(p, f, 5.550332471162809e-2f);
    p = fmaf(p, f, 2.402264791363012e-1f);
    p = fmaf(p, f, 6.931472028550421e-1f);
    p = fmaf(p, f, 1.0f);
    return p * __int_as_float((n + 127) << 23);
}

__device__ __forceinline__ void cpa16(void* s, const void* g) {
    unsigned sa = (unsigned)__cvta_generic_to_shared(s);
    asm volatile("cp.async.cg.shared.global [%0], [%1], 16;" :: "r"(sa), "l"(g));
}
__device__ __forceinline__ void cp_commit() { asm volatile("cp.async.commit_group;"); }
__device__ __forceinline__ void cp_wait0()  { asm volatile("cp.async.wait_group 0;"); }

// ---------------------------------------------------------------------------
// tf32 GEMM: C[M,N] = A[M,K] @ B[N,K]^T (unchanged from round 5)
// ---------------------------------------------------------------------------
#define GS 20
__global__ void __launch_bounds__(128, 2) gemm_tf32_nt(
        const float* __restrict__ A, const float* __restrict__ B,
        float* __restrict__ C, int M, int N, int K) {
    __shared__ float As[128][GS];
    __shared__ float Bs[128][GS];
    const int tid = threadIdx.x, lane = tid & 31;
    const int w   = tid >> 5, wm = w >> 1, wn = w & 1;
    const int g   = lane >> 2, q = lane & 3;
    const int ldR = tid >> 2, ldC = (tid & 3) << 2;

    const float* Ag = A + (size_t)(blockIdx.y * 128 + ldR) * K + ldC;
    const float* Bg = B + (size_t)(blockIdx.x * 128 + ldR) * K + ldC;

    float acc[4][8][4] = {};
    float4 ra[4], rb[4];
    #pragma unroll
    for (int j = 0; j < 4; j++) {
        ra[j] = *(const float4*)(Ag + (size_t)(32 * j) * K);
        rb[j] = *(const float4*)(Bg + (size_t)(32 * j) * K);
    }

    const int nC = K >> 4;
    for (int ch = 0; ch < nC; ch++) {
        #pragma unroll
        for (int j = 0; j < 4; j++) {
            *(float4*)&As[ldR + 32 * j][ldC] =
                make_float4(f2tff(ra[j].x), f2tff(ra[j].y), f2tff(ra[j].z), f2tff(ra[j].w));
            *(float4*)&Bs[ldR + 32 * j][ldC] =
                make_float4(f2tff(rb[j].x), f2tff(rb[j].y), f2tff(rb[j].z), f2tff(rb[j].w));
        }
        __syncthreads();

        Ag += 16; Bg += 16;
        if (ch + 1 < nC) {
            #pragma unroll
            for (int j = 0; j < 4; j++) {
                ra[j] = *(const float4*)(Ag + (size_t)(32 * j) * K);
                rb[j] = *(const float4*)(Bg + (size_t)(32 * j) * K);
            }
        }

        #pragma unroll
        for (int kk = 0; kk < 2; kk++) {
            const int cb = kk * 8 + q;
            unsigned af[4][4], bf[8][2];
            #pragma unroll
            for (int mi = 0; mi < 4; mi++) {
                const int rb2 = wm * 64 + mi * 16;
                af[mi][0] = __float_as_uint(As[rb2 + g][cb]);
                af[mi][1] = __float_as_uint(As[rb2 + 8 + g][cb]);
                af[mi][2] = __float_as_uint(As[rb2 + g][cb + 4]);
                af[mi][3] = __float_as_uint(As[rb2 + 8 + g][cb + 4]);
            }
            #pragma unroll
            for (int ni = 0; ni < 8; ni++) {
                const int nb = wn * 64 + ni * 8;
                bf[ni][0] = __float_as_uint(Bs[nb + g][cb]);
                bf[ni][1] = __float_as_uint(Bs[nb + g][cb + 4]);
            }
            #pragma unroll
            for (int mi = 0; mi < 4; mi++)
                #pragma unroll
                for (int ni = 0; ni < 8; ni++)
                    mma8(acc[mi][ni], af[mi], bf[ni]);
        }
        __syncthreads();
    }

    #pragma unroll
    for (int mi = 0; mi < 4; mi++) {
        const int row = blockIdx.y * 128 + wm * 64 + mi * 16 + g;
        #pragma unroll
        for (int ni = 0; ni < 8; ni++) {
            const int col = blockIdx.x * 128 + wn * 64 + ni * 8 + 2 * q;
            *(float2*)&C[(size_t)row * N + col]       = make_float2(acc[mi][ni][0], acc[mi][ni][1]);
            *(float2*)&C[(size_t)(row + 8) * N + col] = make_float2(acc[mi][ni][2], acc[mi][ni][3]);
        }
    }
}

// ---------------------------------------------------------------------------
// RoPE: q in place (fp32). k -> g_kf fragment-ordered tf32.
// v -> g_vph fp16, paired (rows 2m,2m+1 interleaved as half2).
// Frag order pos(d) = (d&3)*16 + (d>>3)*2 + ((d>>2)&1).
// ---------------------------------------------------------------------------
__global__ void rope_kernel(float* __restrict__ qkv, float* __restrict__ kf,
                            __half* __restrict__ vph) {
    int idx = blockIdx.x * blockDim.x + threadIdx.x;
    if (idx >= TOKENS * NH * 32) return;
    int i     = idx & 31;
    int h     = (idx >> 5) & 15;
    int token = idx >> 9;
    int s     = token & (S_LEN - 1);
    int bh    = ((token >> 11) << 4) | h;

    double invf_d = exp(-((double)i / 32.0) * log(10000.0));
    float  invf   = (float)invf_d;
    float  ang    = (float)s * invf;
    float  c = cosf(ang), sn = sinf(ang);

    size_t base = (size_t)token * (3 * HDIM) + h * 64;
    float q1 = qkv[base + i], q2 = qkv[base + i + 32];
    qkv[base + i]      = q1 * c - q2 * sn;
    qkv[base + i + 32] = q2 * c + q1 * sn;

    float k1 = qkv[base + HDIM + i], k2 = qkv[base + HDIM + i + 32];
    float kr1 = k1 * c - k2 * sn, kr2 = k2 * c + k1 * sn;
    float* kdst = kf + ((size_t)bh * S_LEN + s) * 64;
    int d0 = i, d1 = i + 32;
    kdst[(d0 & 3) * 16 + (d0 >> 3) * 2 + ((d0 >> 2) & 1)] = f2tff(kr1);
    kdst[(d1 & 3) * 16 + (d1 >> 3) * 2 + ((d1 >> 2) & 1)] = f2tff(kr2);

    // V pairs: half index = ((bh*1024 + s/2)*64 + d)*2 + (s&1)
    size_t vb = ((size_t)bh * 1024 + (s >> 1)) * 64;
    float v1 = qkv[base + 2 * HDIM + i], v2 = qkv[base + 2 * HDIM + i + 32];
    vph[(vb + d0) * 2 + (s & 1)] = __float2half_rn(v1);
    vph[(vb + d1) * 2 + (s & 1)] = __float2half_rn(v2);
}

// ---------------------------------------------------------------------------
// Flash attention: tf32 QK + fp16 PV (m16n8k16), causal, fixed-shift base-2
// softmax (no running max). Block = 128 q-rows of one (b,h); 4 warps x 32.
// K frag-ordered (LDS.128), V paired half2. No shuffles: m16n8k8 C-frags map
// same-thread into m16n8k16 A-frags. Double-buffered cp.async.
// ---------------------------------------------------------------------------
#define KST 68              // K row stride (words), 272B: 16B-aligned rows
#define VST 68              // V row stride (half2 words)
__global__ void __launch_bounds__(128, 2) flash2(const float* __restrict__ qkv,
                                                 const float* __restrict__ kf,
                                                 const __half2* __restrict__ vp,
                                                 float* __restrict__ out) {
    extern __shared__ float sm[];
    float*   KsB = sm;                        // [2][64][KST] floats
    __half2* VsB = (__half2*)(sm + 2 * 64 * KST);  // [2][32][VST] half2

    const int tid = threadIdx.x, lane = tid & 31, w = tid >> 5;
    const int g   = lane >> 2, q = lane & 3;
    const int qb  = gridDim.x - 1 - blockIdx.x;       // heavy blocks first
    const int bh  = blockIdx.y;
    const int b   = bh >> 4, h = bh & 15;
    const int r0  = qb * 128 + w * 32;

    // ---- Q fragments, scaled by (1/8)*log2(e)
    const float SC = 0.125f * 1.44269504088896340736f;
    unsigned qf[2][8][4];
    #pragma unroll
    for (int mi = 0; mi < 2; mi++) {
        const size_t bl = (size_t)(b * S_LEN + r0 + mi * 16 + g) * 3072 + h * 64;
        const size_t bhh = bl + (size_t)8 * 3072;
        #pragma unroll
        for (int kk = 0; kk < 8; kk++) {
            const int c = kk * 8 + q;
            qf[mi][kk][0] = f2tf(qkv[bl + c] * SC);
            qf[mi][kk][1] = f2tf(qkv[bhh + c] * SC);
            qf[mi][kk][2] = f2tf(qkv[bl + c + 4] * SC);
            qf[mi][kk][3] = f2tf(qkv[bhh + c + 4] * SC);
        }
    }

    float acc[2][8][4] = {};
    float l_[2][2] = {};

    const float*   Kpl = kf + (size_t)bh * S_LEN * 64;
    const __half2* Vpl = vp + (size_t)bh * 1024 * 64;

    // cp.async mappings
    const int kR = tid >> 1, kH = (tid & 1) * 32;     // K: row 0..63, half-row
    const int vR = tid >> 2, vC = (tid & 3) * 16;     // V: pair-row 0..31, quarter
    const int jmax = 2 * qb + 1;

    // prefetch tile 0
    {
        const float*   ks = Kpl + (size_t)kR * 64 + kH;
        const __half2* vs = Vpl + (size_t)vR * 64 + vC;
        #pragma unroll
        for (int i = 0; i < 8; i++) cpa16(KsB + kR * KST + kH + 4 * i, ks + 4 * i);
        #pragma unroll
        for (int i = 0; i < 4; i++) cpa16(VsB + vR * VST + vC + 4 * i, vs + 4 * i);
    }
    cp_commit();

    for (int jb = 0; jb <= jmax; jb++) {
        cp_wait0();
        __syncthreads();

        if (jb < jmax) {
            const int nb = (jb + 1) & 1;
            const float*   ks = Kpl + (size_t)((jb + 1) * 64 + kR) * 64 + kH;
            const __half2* vs = Vpl + (size_t)((jb + 1) * 32 + vR) * 64 + vC;
            #pragma unroll
            for (int i = 0; i < 8; i++) cpa16(KsB + (nb * 64 + kR) * KST + kH + 4 * i, ks + 4 * i);
            #pragma unroll
            for (int i = 0; i < 4; i++) cpa16(VsB + (nb * 32 + vR) * VST + vC + 4 * i, vs + 4 * i);
            cp_commit();
        }

        if (r0 + 31 >= jb * 64) {
            const float*   K = KsB + (jb & 1) * 64 * KST;
            const __half2* V = VsB + (jb & 1) * 32 * VST;

            // ---- S = Q @ K^T (K via LDS.128, frag-ordered rows)
            float p[2][8][4];
            #pragma unroll
            for (int n = 0; n < 8; n++) {
                float s0[4] = {}, s1[4] = {};
                const float4* krow = (const float4*)(K + (n * 8 + g) * KST) + q * 4;
                #pragma unroll
                for (int c = 0; c < 4; c++) {
                    float4 f = krow[c];
                    unsigned b0[2] = { __float_as_uint(f.x), __float_as_uint(f.y) };
                    unsigned b1[2] = { __float_as_uint(f.z), __float_as_uint(f.w) };
                    mma8(s0, qf[0][2 * c], b0);
                    mma8(s0, qf[0][2 * c + 1], b1);
                    mma8(s1, qf[1][2 * c], b0);
                    mma8(s1, qf[1][2 * c + 1], b1);
                }
                #pragma unroll
                for (int e = 0; e < 4; e++) { p[0][n][e] = s0[e]; p[1][n][e] = s1[e]; }
            }

            // ---- causal mask (diagonal region only)
            if (jb * 64 + 63 > r0) {
                #pragma unroll
                for (int mi = 0; mi < 2; mi++) {
                    const int rL = r0 + mi * 16 + g, rH = rL + 8;
                    #pragma unroll
                    for (int n = 0; n < 8; n++) {
                        const int c0 = jb * 64 + n * 8 + 2 * q;
                        if (c0 > rL)     p[mi][n][0] = -1e30f;
                        if (c0 + 1 > rL) p[mi][n][1] = -1e30f;
                        if (c0 > rH)     p[mi][n][2] = -1e30f;
                        if (c0 + 1 > rH) p[mi][n][3] = -1e30f;
                    }
                }
            }

            // ---- fixed-shift softmax: p = 2^s, accumulate l (no max, no rescale)
            #pragma unroll
            for (int mi = 0; mi < 2; mi++) {
                float sum0 = 0.f, sum1 = 0.f;
                #pragma unroll
                for (int n = 0; n < 8; n++) {
                    p[mi][n][0] = fexp2(p[mi][n][0]);
                    p[mi][n][1] = fexp2(p[mi][n][1]);
                    p[mi][n][2] = fexp2(p[mi][n][2]);
                    p[mi][n][3] = fexp2(p[mi][n][3]);
                    sum0 += p[mi][n][0] + p[mi][n][1];
                    sum1 += p[mi][n][2] + p[mi][n][3];
                }
                l_[mi][0] += sum0;
                l_[mi][1] += sum1;
            }

            // ---- acc += P @ V (fp16 m16n8k16; A-frags same-thread from C-frags)
            #pragma unroll
            for (int t = 0; t < 4; t++) {
                unsigned pa[2][4];
                #pragma unroll
                for (int mi = 0; mi < 2; mi++) {
                    pa[mi][0] = pkh2(p[mi][2 * t][1],     p[mi][2 * t][0]);
                    pa[mi][1] = pkh2(p[mi][2 * t][3],     p[mi][2 * t][2]);
                    pa[mi][2] = pkh2(p[mi][2 * t + 1][1], p[mi][2 * t + 1][0]);
                    pa[mi][3] = pkh2(p[mi][2 * t + 1][3], p[mi][2 * t + 1][2]);
                }
                #pragma unroll
                for (int n = 0; n < 8; n++) {
                    unsigned vb[2] = {
                        *(const unsigned*)&V[(t * 8 + q) * VST + n * 8 + g],
                        *(const unsigned*)&V[(t * 8 + q + 4) * VST + n * 8 + g] };
                    hmma16(acc[0][n], pa[0], vb);
                    hmma16(acc[1][n], pa[1], vb);
                }
            }
        }
    }

    // ---- reduce l across quad lanes, normalize + write
    #pragma unroll
    for (int mi = 0; mi < 2; mi++) {
        float l0 = l_[mi][0], l1 = l_[mi][1];
        l0 += __shfl_xor_sync(0xffffffffu, l0, 1);
        l0 += __shfl_xor_sync(0xffffffffu, l0, 2);
        l1 += __shfl_xor_sync(0xffffffffu, l1, 1);
        l1 += __shfl_xor_sync(0xffffffffu, l1, 2);
        const float inv0 = 1.f / l0, inv1 = 1.f / l1;
        const size_t tokL = (size_t)(b * S_LEN + r0 + mi * 16 + g);
        const size_t tokH = tokL + 8;
        #pragma unroll
        for (int n = 0; n < 8; n++) {
            const int c = h * 64 + n * 8 + 2 * q;
            *(float2*)&out[tokL * HDIM + c] = make_float2(acc[mi][n][0] * inv0, acc[mi][n][1] * inv0);
            *(float2*)&out[tokH * HDIM + c] = make_float2(acc[mi][n][2] * inv1, acc[mi][n][3] * inv1);
        }
    }
}

// ---------------------------------------------------------------------------
// Launch
// ---------------------------------------------------------------------------
extern "C" void kernel_launch(void* const* d_in, const int* in_sizes, int n_in,
                              void* d_out, int out_size) {
    const float* x     = (const float*)d_in[0];
    const float* w_qkv = (const float*)d_in[1];
    const float* w_o   = (const float*)d_in[2];
    float* out = (float*)d_out;

    float *qkv, *att, *kf; __half* vph;
    cudaGetSymbolAddress((void**)&qkv, g_qkv);
    cudaGetSymbolAddress((void**)&att, g_att);
    cudaGetSymbolAddress((void**)&kf,  g_kf);
    cudaGetSymbolAddress((void**)&vph, g_vph);

    // 1) QKV projection
    gemm_tf32_nt<<<dim3(3 * HDIM / 128, TOKENS / 128), 128>>>(x, w_qkv, qkv, TOKENS, 3 * HDIM, HDIM);

    // 2) RoPE + K frag-reorder (tf32) + V fp16 pairing
    rope_kernel<<<(TOKENS * NH * 32) / 256, 256>>>(qkv, kf, vph);

    // 3) Causal flash attention
    const int flash_smem = (2 * 64 * KST + 2 * 32 * VST) * 4;  // 52224 B
    cudaFuncSetAttribute(flash2, cudaFuncAttributeMaxDynamicSharedMemorySize, flash_smem);
    flash2<<<dim3(S_LEN / 128, 2 * NH), 128, flash_smem>>>(qkv, kf, (const __half2*)vph, att);

    // 4) Output projection
    gemm_tf32_nt<<<dim3(HDIM / 128, TOKENS / 128), 128>>>(att, w_o, out, TOKENS, HDIM, HDIM);
}

// round 8
// speedup vs baseline: 4.1057x; 1.2621x over previous
#include <cuda_runtime.h>
#include <cuda_fp16.h>
#include <math.h>

#define TOKENS 4096      // B*S = 2*2048
#define S_LEN  2048
#define HDIM   1024
#define NH     16

// Scratch (static device globals — no allocations allowed)
__device__ __align__(256) float  g_qkv[(size_t)TOKENS * 3 * HDIM]; // [token][3*1024]
__device__ __align__(256) float  g_att[(size_t)TOKENS * HDIM];
__device__ __align__(256) __half g_kh [(size_t)32 * S_LEN * 64];   // K fp16 frag-ordered
__device__ __align__(256) __half g_vph[(size_t)32 * 1024 * 64 * 2]; // V half2 pairs

// ---------------------------------------------------------------------------
// Helpers
// ---------------------------------------------------------------------------
__device__ __forceinline__ unsigned f2tf(float x) {
    unsigned r; asm("cvt.rna.tf32.f32 %0, %1;" : "=r"(r) : "f"(x)); return r;
}
__device__ __forceinline__ float f2tff(float x) { return __uint_as_float(f2tf(x)); }

__device__ __forceinline__ void mma8(float* c, const unsigned* a, const unsigned* b) {
    asm("mma.sync.aligned.m16n8k8.row.col.f32.tf32.tf32.f32 "
        "{%0,%1,%2,%3}, {%4,%5,%6,%7}, {%8,%9}, {%0,%1,%2,%3};"
        : "+f"(c[0]), "+f"(c[1]), "+f"(c[2]), "+f"(c[3])
        : "r"(a[0]), "r"(a[1]), "r"(a[2]), "r"(a[3]), "r"(b[0]), "r"(b[1]));
}
__device__ __forceinline__ void hmma16(float* c, const unsigned* a, const unsigned* b) {
    asm("mma.sync.aligned.m16n8k16.row.col.f32.f16.f16.f32 "
        "{%0,%1,%2,%3}, {%4,%5,%6,%7}, {%8,%9}, {%0,%1,%2,%3};"
        : "+f"(c[0]), "+f"(c[1]), "+f"(c[2]), "+f"(c[3])
        : "r"(a[0]), "r"(a[1]), "r"(a[2]), "r"(a[3]), "r"(b[0]), "r"(b[1]));
}
__device__ __forceinline__ unsigned pkh2(float hi, float lo) {
    unsigned d; asm("cvt.rn.f16x2.f32 %0, %1, %2;" : "=r"(d) : "f"(hi), "f"(lo)); return d;
}
// MUFU exp2 (~2^-21 rel err; saturates to +0 for very negative inputs)
__device__ __forceinline__ float ex2(float x) {
    float y; asm("ex2.approx.f32 %0, %1;" : "=f"(y) : "f"(x)); return y;
}

__device__ __forceinline__ void cpa16(void* s, const void* g) {
    unsigned sa = (unsigned)__cvta_generic_to_shared(s);
    asm volatile("cp.async.cg.shared.global [%0], [%1], 16;" :: "r"(sa), "l"(g));
}
__device__ __forceinline__ void cp_commit() { asm volatile("cp.async.commit_group;"); }
__device__ __forceinline__ void cp_wait0()  { asm volatile("cp.async.wait_group 0;"); }

// ---------------------------------------------------------------------------
// tf32 GEMM: C[M,N] = A[M,K] @ B[N,K]^T (unchanged, verified)
// ---------------------------------------------------------------------------
#define GS 20
__global__ void __launch_bounds__(128, 2) gemm_tf32_nt(
        const float* __restrict__ A, const float* __restrict__ B,
        float* __restrict__ C, int M, int N, int K) {
    __shared__ float As[128][GS];
    __shared__ float Bs[128][GS];
    const int tid = threadIdx.x, lane = tid & 31;
    const int w   = tid >> 5, wm = w >> 1, wn = w & 1;
    const int g   = lane >> 2, q = lane & 3;
    const int ldR = tid >> 2, ldC = (tid & 3) << 2;

    const float* Ag = A + (size_t)(blockIdx.y * 128 + ldR) * K + ldC;
    const float* Bg = B + (size_t)(blockIdx.x * 128 + ldR) * K + ldC;

    float acc[4][8][4] = {};
    float4 ra[4], rb[4];
    #pragma unroll
    for (int j = 0; j < 4; j++) {
        ra[j] = *(const float4*)(Ag + (size_t)(32 * j) * K);
        rb[j] = *(const float4*)(Bg + (size_t)(32 * j) * K);
    }

    const int nC = K >> 4;
    for (int ch = 0; ch < nC; ch++) {
        #pragma unroll
        for (int j = 0; j < 4; j++) {
            *(float4*)&As[ldR + 32 * j][ldC] =
                make_float4(f2tff(ra[j].x), f2tff(ra[j].y), f2tff(ra[j].z), f2tff(ra[j].w));
            *(float4*)&Bs[ldR + 32 * j][ldC] =
                make_float4(f2tff(rb[j].x), f2tff(rb[j].y), f2tff(rb[j].z), f2tff(rb[j].w));
        }
        __syncthreads();

        Ag += 16; Bg += 16;
        if (ch + 1 < nC) {
            #pragma unroll
            for (int j = 0; j < 4; j++) {
                ra[j] = *(const float4*)(Ag + (size_t)(32 * j) * K);
                rb[j] = *(const float4*)(Bg + (size_t)(32 * j) * K);
            }
        }

        #pragma unroll
        for (int kk = 0; kk < 2; kk++) {
            const int cb = kk * 8 + q;
            unsigned af[4][4], bf[8][2];
            #pragma unroll
            for (int mi = 0; mi < 4; mi++) {
                const int rb2 = wm * 64 + mi * 16;
                af[mi][0] = __float_as_uint(As[rb2 + g][cb]);
                af[mi][1] = __float_as_uint(As[rb2 + 8 + g][cb]);
                af[mi][2] = __float_as_uint(As[rb2 + g][cb + 4]);
                af[mi][3] = __float_as_uint(As[rb2 + 8 + g][cb + 4]);
            }
            #pragma unroll
            for (int ni = 0; ni < 8; ni++) {
                const int nb = wn * 64 + ni * 8;
                bf[ni][0] = __float_as_uint(Bs[nb + g][cb]);
                bf[ni][1] = __float_as_uint(Bs[nb + g][cb + 4]);
            }
            #pragma unroll
            for (int mi = 0; mi < 4; mi++)
                #pragma unroll
                for (int ni = 0; ni < 8; ni++)
                    mma8(acc[mi][ni], af[mi], bf[ni]);
        }
        __syncthreads();
    }

    #pragma unroll
    for (int mi = 0; mi < 4; mi++) {
        const int row = blockIdx.y * 128 + wm * 64 + mi * 16 + g;
        #pragma unroll
        for (int ni = 0; ni < 8; ni++) {
            const int col = blockIdx.x * 128 + wn * 64 + ni * 8 + 2 * q;
            *(float2*)&C[(size_t)row * N + col]       = make_float2(acc[mi][ni][0], acc[mi][ni][1]);
            *(float2*)&C[(size_t)(row + 8) * N + col] = make_float2(acc[mi][ni][2], acc[mi][ni][3]);
        }
    }
}

// ---------------------------------------------------------------------------
// RoPE: q in place (fp32). k -> g_kh fp16 in m16n8k16 B-frag order:
//   pos(d) = ((d&7)>>1)*16 + (d>>4)*4 + ((d>>3)&1)*2 + (d&1)
// v -> g_vph fp16, paired (rows 2m,2m+1 interleaved as half2).
// ---------------------------------------------------------------------------
__global__ void rope_kernel(float* __restrict__ qkv, __half* __restrict__ kh,
                            __half* __restrict__ vph) {
    int idx = blockIdx.x * blockDim.x + threadIdx.x;
    if (idx >= TOKENS * NH * 32) return;
    int i     = idx & 31;
    int h     = (idx >> 5) & 15;
    int token = idx >> 9;
    int s     = token & (S_LEN - 1);
    int bh    = ((token >> 11) << 4) | h;

    double invf_d = exp(-((double)i / 32.0) * log(10000.0));
    float  invf   = (float)invf_d;
    float  ang    = (float)s * invf;
    float  c = cosf(ang), sn = sinf(ang);

    size_t base = (size_t)token * (3 * HDIM) + h * 64;
    float q1 = qkv[base + i], q2 = qkv[base + i + 32];
    qkv[base + i]      = q1 * c - q2 * sn;
    qkv[base + i + 32] = q2 * c + q1 * sn;

    float k1 = qkv[base + HDIM + i], k2 = qkv[base + HDIM + i + 32];
    float kr1 = k1 * c - k2 * sn, kr2 = k2 * c + k1 * sn;
    __half* kdst = kh + ((size_t)bh * S_LEN + s) * 64;
    int d0 = i, d1 = i + 32;
    #pragma unroll
    for (int e = 0; e < 2; e++) {
        int d = e ? d1 : d0;
        float v = e ? kr2 : kr1;
        int pos = ((d & 7) >> 1) * 16 + (d >> 4) * 4 + ((d >> 3) & 1) * 2 + (d & 1);
        kdst[pos] = __float2half_rn(v);
    }

    // V pairs: half index = ((bh*1024 + s/2)*64 + d)*2 + (s&1)
    size_t vb = ((size_t)bh * 1024 + (s >> 1)) * 64;
    float v1 = qkv[base + 2 * HDIM + i], v2 = qkv[base + 2 * HDIM + i + 32];
    vph[(vb + d0) * 2 + (s & 1)] = __float2half_rn(v1);
    vph[(vb + d1) * 2 + (s & 1)] = __float2half_rn(v2);
}

// ---------------------------------------------------------------------------
// Flash attention: fp16 QK + fp16 PV (m16n8k16), causal, fixed-shift base-2
// softmax via MUFU ex2 (no running max). Block = 128 q-rows of one (b,h);
// 4 warps x 32 rows. K frag-ordered fp16 (2 LDS.128 per 8-key block),
// V paired half2. QK C-frags feed PV A-frags same-thread. cp.async x2 buf.
// ---------------------------------------------------------------------------
#define KH  72              // K row stride (halves): 144B rows, phase-conflict-free
#define VST 68              // V row stride (half2 words)
__global__ void __launch_bounds__(128, 2) flash2(const float* __restrict__ qkv,
                                                 const __half* __restrict__ kh,
                                                 const __half2* __restrict__ vp,
                                                 float* __restrict__ out) {
    extern __shared__ float sm[];
    __half*  KsB = (__half*)sm;                         // [2][64][KH] halves
    __half2* VsB = (__half2*)(sm + (2 * 64 * KH) / 2);  // [2][32][VST] half2

    const int tid = threadIdx.x, lane = tid & 31, w = tid >> 5;
    const int g   = lane >> 2, q = lane & 3;
    const int qb  = gridDim.x - 1 - blockIdx.x;       // heavy blocks first
    const int bh  = blockIdx.y;
    const int b   = bh >> 4, h = bh & 15;
    const int r0  = qb * 128 + w * 32;

    // ---- Q fp16 A-fragments (m16n8k16), scaled by (1/8)*log2(e)
    const float SC = 0.125f * 1.44269504088896340736f;
    unsigned qa[2][4][4];
    #pragma unroll
    for (int mi = 0; mi < 2; mi++) {
        const float* rl = qkv + (size_t)(b * S_LEN + r0 + mi * 16 + g) * 3072 + h * 64;
        const float* rh = rl + (size_t)8 * 3072;
        #pragma unroll
        for (int kg = 0; kg < 4; kg++) {
            float2 lo0 = *(const float2*)(rl + kg * 16 + 2 * q);
            float2 hi0 = *(const float2*)(rh + kg * 16 + 2 * q);
            float2 lo8 = *(const float2*)(rl + kg * 16 + 8 + 2 * q);
            float2 hi8 = *(const float2*)(rh + kg * 16 + 8 + 2 * q);
            qa[mi][kg][0] = pkh2(lo0.y * SC, lo0.x * SC);
            qa[mi][kg][1] = pkh2(hi0.y * SC, hi0.x * SC);
            qa[mi][kg][2] = pkh2(lo8.y * SC, lo8.x * SC);
            qa[mi][kg][3] = pkh2(hi8.y * SC, hi8.x * SC);
        }
    }

    float acc[2][8][4] = {};
    float l_[2][2] = {};

    const __half*  Kpl = kh + (size_t)bh * S_LEN * 64;
    const __half2* Vpl = vp + (size_t)bh * 1024 * 64;

    // cp.async mappings: K 8KB/tile (4x16B per thread), V 8KB/tile
    const int kR = tid >> 3, kC = (tid & 7) * 8;      // K: row 0..15(x4), 8-half col
    const int vR = tid >> 2, vC = (tid & 3) * 16;     // V: pair-row, quarter
    const int jmax = 2 * qb + 1;

    {
        #pragma unroll
        for (int i = 0; i < 4; i++)
            cpa16(KsB + (kR + i * 16) * KH + kC, Kpl + (size_t)(kR + i * 16) * 64 + kC);
        #pragma unroll
        for (int i = 0; i < 4; i++)
            cpa16(VsB + vR * VST + vC + 4 * i, Vpl + (size_t)vR * 64 + vC + 4 * i);
    }
    cp_commit();

    for (int jb = 0; jb <= jmax; jb++) {
        cp_wait0();
        __syncthreads();

        if (jb < jmax) {
            const int nb = (jb + 1) & 1;
            const __half*  ks = Kpl + (size_t)((jb + 1) * 64) * 64;
            const __half2* vs = Vpl + (size_t)((jb + 1) * 32 + vR) * 64 + vC;
            #pragma unroll
            for (int i = 0; i < 4; i++)
                cpa16(KsB + (nb * 64 + kR + i * 16) * KH + kC, ks + (size_t)(kR + i * 16) * 64 + kC);
            #pragma unroll
            for (int i = 0; i < 4; i++)
                cpa16(VsB + (nb * 32 + vR) * VST + vC + 4 * i, vs + 4 * i);
            cp_commit();
        }

        if (r0 + 31 >= jb * 64) {
            const __half*  K = KsB + (jb & 1) * 64 * KH;
            const __half2* V = VsB + (jb & 1) * 32 * VST;

            // ---- S = Q @ K^T (fp16 m16n8k16; 2 LDS.128 per 8-key block)
            float p[2][8][4];
            #pragma unroll
            for (int n = 0; n < 8; n++) {
                float s0[4] = {}, s1[4] = {};
                const uint4* krow = (const uint4*)(K + (n * 8 + g) * KH + q * 16);
                uint4 k0 = krow[0];   // kg0: {x,y}, kg1: {z,w}
                uint4 k1 = krow[1];   // kg2: {x,y}, kg3: {z,w}
                unsigned b0[2] = { k0.x, k0.y }, b1[2] = { k0.z, k0.w };
                unsigned b2[2] = { k1.x, k1.y }, b3[2] = { k1.z, k1.w };
                hmma16(s0, qa[0][0], b0); hmma16(s0, qa[0][1], b1);
                hmma16(s0, qa[0][2], b2); hmma16(s0, qa[0][3], b3);
                hmma16(s1, qa[1][0], b0); hmma16(s1, qa[1][1], b1);
                hmma16(s1, qa[1][2], b2); hmma16(s1, qa[1][3], b3);
                #pragma unroll
                for (int e = 0; e < 4; e++) { p[0][n][e] = s0[e]; p[1][n][e] = s1[e]; }
            }

            // ---- causal mask (diagonal region only)
            if (jb * 64 + 63 > r0) {
                #pragma unroll
                for (int mi = 0; mi < 2; mi++) {
                    const int rL = r0 + mi * 16 + g, rH = rL + 8;
                    #pragma unroll
                    for (int n = 0; n < 8; n++) {
                        const int c0 = jb * 64 + n * 8 + 2 * q;
                        if (c0 > rL)     p[mi][n][0] = -1e30f;
                        if (c0 + 1 > rL) p[mi][n][1] = -1e30f;
                        if (c0 > rH)     p[mi][n][2] = -1e30f;
                        if (c0 + 1 > rH) p[mi][n][3] = -1e30f;
                    }
                }
            }

            // ---- fixed-shift softmax: p = 2^s via MUFU, accumulate l
            #pragma unroll
            for (int mi = 0; mi < 2; mi++) {
                float sum0 = 0.f, sum1 = 0.f;
                #pragma unroll
                for (int n = 0; n < 8; n++) {
                    p[mi][n][0] = ex2(p[mi][n][0]);
                    p[mi][n][1] = ex2(p[mi][n][1]);
                    p[mi][n][2] = ex2(p[mi][n][2]);
                    p[mi][n][3] = ex2(p[mi][n][3]);
                    sum0 += p[mi][n][0] + p[mi][n][1];
                    sum1 += p[mi][n][2] + p[mi][n][3];
                }
                l_[mi][0] += sum0;
                l_[mi][1] += sum1;
            }

            // ---- acc += P @ V (fp16; A-frags same-thread from C-frags)
            #pragma unroll
            for (int t = 0; t < 4; t++) {
                unsigned pa[2][4];
                #pragma unroll
                for (int mi = 0; mi < 2; mi++) {
                    pa[mi][0] = pkh2(p[mi][2 * t][1],     p[mi][2 * t][0]);
                    pa[mi][1] = pkh2(p[mi][2 * t][3],     p[mi][2 * t][2]);
                    pa[mi][2] = pkh2(p[mi][2 * t + 1][1], p[mi][2 * t + 1][0]);
                    pa[mi][3] = pkh2(p[mi][2 * t + 1][3], p[mi][2 * t + 1][2]);
                }
                #pragma unroll
                for (int n = 0; n < 8; n++) {
                    unsigned vb[2] = {
                        *(const unsigned*)&V[(t * 8 + q) * VST + n * 8 + g],
                        *(const unsigned*)&V[(t * 8 + q + 4) * VST + n * 8 + g] };
                    hmma16(acc[0][n], pa[0], vb);
                    hmma16(acc[1][n], pa[1], vb);
                }
            }
        }
    }

    // ---- reduce l across quad lanes, normalize + write
    #pragma unroll
    for (int mi = 0; mi < 2; mi++) {
        float l0 = l_[mi][0], l1 = l_[mi][1];
        l0 += __shfl_xor_sync(0xffffffffu, l0, 1);
        l0 += __shfl_xor_sync(0xffffffffu, l0, 2);
        l1 += __shfl_xor_sync(0xffffffffu, l1, 1);
        l1 += __shfl_xor_sync(0xffffffffu, l1, 2);
        const float inv0 = 1.f / l0, inv1 = 1.f / l1;
        const size_t tokL = (size_t)(b * S_LEN + r0 + mi * 16 + g);
        const size_t tokH = tokL + 8;
        #pragma unroll
        for (int n = 0; n < 8; n++) {
            const int c = h * 64 + n * 8 + 2 * q;
            *(float2*)&out[tokL * HDIM + c] = make_float2(acc[mi][n][0] * inv0, acc[mi][n][1] * inv0);
            *(float2*)&out[tokH * HDIM + c] = make_float2(acc[mi][n][2] * inv1, acc[mi][n][3] * inv1);
        }
    }
}

// ---------------------------------------------------------------------------
// Launch
// ---------------------------------------------------------------------------
extern "C" void kernel_launch(void* const* d_in, const int* in_sizes, int n_in,
                              void* d_out, int out_size) {
    const float* x     = (const float*)d_in[0];
    const float* w_qkv = (const float*)d_in[1];
    const float* w_o   = (const float*)d_in[2];
    float* out = (float*)d_out;

    float *qkv, *att; __half *khp, *vph;
    cudaGetSymbolAddress((void**)&qkv, g_qkv);
    cudaGetSymbolAddress((void**)&att, g_att);
    cudaGetSymbolAddress((void**)&khp, g_kh);
    cudaGetSymbolAddress((void**)&vph, g_vph);

    // 1) QKV projection
    gemm_tf32_nt<<<dim3(3 * HDIM / 128, TOKENS / 128), 128>>>(x, w_qkv, qkv, TOKENS, 3 * HDIM, HDIM);

    // 2) RoPE + K fp16 frag-reorder + V fp16 pairing
    rope_kernel<<<(TOKENS * NH * 32) / 256, 256>>>(qkv, khp, vph);

    // 3) Causal flash attention (fp16 tensor cores)
    const int flash_smem = 2 * 64 * KH * 2 + 2 * 32 * VST * 4;  // 35840 B
    cudaFuncSetAttribute(flash2, cudaFuncAttributeMaxDynamicSharedMemorySize, flash_smem);
    flash2<<<dim3(S_LEN / 128, 2 * NH), 128, flash_smem>>>(qkv, khp, (const __half2*)vph, att);

    // 4) Output projection
    gemm_tf32_nt<<<dim3(HDIM / 128, TOKENS / 128), 128>>>(att, w_o, out, TOKENS, HDIM, HDIM);
}

// round 9
// speedup vs baseline: 4.8668x; 1.1854x over previous
#include <cuda_runtime.h>
#include <cuda_fp16.h>
#include <math.h>

#define TOKENS 4096      // B*S = 2*2048
#define S_LEN  2048
#define HDIM   1024
#define NH     16

// Scratch (static device globals — no allocations allowed)
__device__ __align__(256) float  g_qkv[(size_t)TOKENS * 3 * HDIM]; // [token][3*1024]
__device__ __align__(256) __half g_xh [(size_t)TOKENS * HDIM];     // x in fp16
__device__ __align__(256) __half g_wqh[(size_t)3 * HDIM * HDIM];   // w_qkv fp16
__device__ __align__(256) __half g_woh[(size_t)HDIM * HDIM];       // w_o fp16
__device__ __align__(256) __half g_ath[(size_t)TOKENS * HDIM];     // att fp16
__device__ __align__(256) __half g_kh [(size_t)32 * S_LEN * 64];   // K fp16 frag-ordered
__device__ __align__(256) __half g_vph[(size_t)32 * 1024 * 64 * 2]; // V half2 pairs

// ---------------------------------------------------------------------------
// Helpers
// ---------------------------------------------------------------------------
__device__ __forceinline__ float f2tff(float x) {
    unsigned r; asm("cvt.rna.tf32.f32 %0, %1;" : "=r"(r) : "f"(x));
    return __uint_as_float(r);
}
__device__ __forceinline__ void hmma16(float* c, const unsigned* a, const unsigned* b) {
    asm("mma.sync.aligned.m16n8k16.row.col.f32.f16.f16.f32 "
        "{%0,%1,%2,%3}, {%4,%5,%6,%7}, {%8,%9}, {%0,%1,%2,%3};"
        : "+f"(c[0]), "+f"(c[1]), "+f"(c[2]), "+f"(c[3])
        : "r"(a[0]), "r"(a[1]), "r"(a[2]), "r"(a[3]), "r"(b[0]), "r"(b[1]));
}
__device__ __forceinline__ unsigned pkh2(float hi, float lo) {
    unsigned d; asm("cvt.rn.f16x2.f32 %0, %1, %2;" : "=r"(d) : "f"(hi), "f"(lo)); return d;
}
__device__ __forceinline__ float ex2(float x) {
    float y; asm("ex2.approx.f32 %0, %1;" : "=f"(y) : "f"(x)); return y;
}
__device__ __forceinline__ void cpa16(void* s, const void* g) {
    unsigned sa = (unsigned)__cvta_generic_to_shared(s);
    asm volatile("cp.async.cg.shared.global [%0], [%1], 16;" :: "r"(sa), "l"(g));
}
__device__ __forceinline__ void cp_commit() { asm volatile("cp.async.commit_group;"); }
__device__ __forceinline__ void cp_wait0()  { asm volatile("cp.async.wait_group 0;"); }
__device__ __forceinline__ void ldmx4(unsigned* r, unsigned addr) {
    asm volatile("ldmatrix.sync.aligned.m8n8.x4.shared.b16 {%0,%1,%2,%3}, [%4];"
        : "=r"(r[0]), "=r"(r[1]), "=r"(r[2]), "=r"(r[3]) : "r"(addr));
}

// ---------------------------------------------------------------------------
// fp32 -> fp16 convert (pre-pass)
// ---------------------------------------------------------------------------
__global__ void cvt_h(const float* __restrict__ s, __half* __restrict__ d, int n4) {
    int i = blockIdx.x * blockDim.x + threadIdx.x;
    if (i >= n4) return;
    float4 v = ((const float4*)s)[i];
    ((uint2*)d)[i] = make_uint2(pkh2(v.y, v.x), pkh2(v.w, v.z));
}

// ---------------------------------------------------------------------------
// fp16 GEMM: C[M,N] = A[M,K] @ B[N,K]^T (f32 accum/out). 128x128 block tile,
// BK=64 halves, 4 warps (2x2), warp 64x64. cp.async double-buffered smem,
// XOR-swizzled rows (8x16B groups, grp^row&7) -> conflict-free ldmatrix.x4.
// ---------------------------------------------------------------------------
__global__ void __launch_bounds__(128, 2) gemm_h_nt(
        const __half* __restrict__ A, const __half* __restrict__ B,
        float* __restrict__ C, int M, int N, int K) {
    extern __shared__ char smx[];   // [2][A 16KB | B 16KB]
    const int tid = threadIdx.x, lane = tid & 31;
    const int w   = tid >> 5, wm = w >> 1, wn = w & 1;
    const int g   = lane >> 2, q = lane & 3;

    const __half* Ag = A + (size_t)(blockIdx.y * 128 + tid) * K;
    const __half* Bg = B + (size_t)(blockIdx.x * 128 + tid) * K;
    const unsigned sbase = (unsigned)__cvta_generic_to_shared(smx);

    // ldmatrix per-lane row bases (row&7 == lane&7 for both A and B)
    const int lrow = ((lane >> 3) & 1) * 8 + (lane & 7);
    const unsigned rbA = sbase + (unsigned)(wm * 64 + lrow) * 128;
    const unsigned rbB = sbase + 16384u + (unsigned)(wn * 64 + lrow) * 128;
    const int gsel = lane >> 4;           // 0/1: lo/hi 16B group of the kg pair
    const int r7   = lane & 7;

    float acc[4][8][4] = {};

    // prefetch stage 0
    {
        char* As = smx; char* Bs = smx + 16384;
        #pragma unroll
        for (int i = 0; i < 8; i++) {
            cpa16(As + tid * 128 + ((i ^ (tid & 7)) * 16), Ag + i * 8);
            cpa16(Bs + tid * 128 + ((i ^ (tid & 7)) * 16), Bg + i * 8);
        }
    }
    cp_commit();

    const int nS = K >> 6;               // 16 stages
    for (int s = 0; s < nS; s++) {
        cp_wait0();
        __syncthreads();

        if (s + 1 < nS) {
            char* As = smx + ((s + 1) & 1) * 32768;
            char* Bs = As + 16384;
            const __half* a = Ag + (s + 1) * 64;
            const __half* b = Bg + (s + 1) * 64;
            #pragma unroll
            for (int i = 0; i < 8; i++) {
                cpa16(As + tid * 128 + ((i ^ (tid & 7)) * 16), a + i * 8);
                cpa16(Bs + tid * 128 + ((i ^ (tid & 7)) * 16), b + i * 8);
            }
            cp_commit();
        }

        const unsigned so = (unsigned)((s & 1) * 32768);
        #pragma unroll
        for (int kgi = 0; kgi < 4; kgi++) {
            const unsigned xo = (unsigned)((((kgi << 1) | gsel) ^ r7) * 16);
            unsigned af[4][4], bf[4][4];
            #pragma unroll
            for (int mb = 0; mb < 4; mb++) ldmx4(af[mb], rbA + so + mb * 2048 + xo);
            #pragma unroll
            for (int np = 0; np < 4; np++) ldmx4(bf[np], rbB + so + np * 2048 + xo);
            #pragma unroll
            for (int mb = 0; mb < 4; mb++)
                #pragma unroll
                for (int ni = 0; ni < 8; ni++) {
                    unsigned bb[2] = { bf[ni >> 1][ni & 1], bf[ni >> 1][(ni & 1) + 2] };
                    hmma16(acc[mb][ni], af[mb], bb);
                }
        }
        __syncthreads();
    }

    #pragma unroll
    for (int mb = 0; mb < 4; mb++) {
        const int row = blockIdx.y * 128 + wm * 64 + mb * 16 + g;
        #pragma unroll
        for (int ni = 0; ni < 8; ni++) {
            const int col = blockIdx.x * 128 + wn * 64 + ni * 8 + 2 * q;
            *(float2*)&C[(size_t)row * N + col]       = make_float2(acc[mb][ni][0], acc[mb][ni][1]);
            *(float2*)&C[(size_t)(row + 8) * N + col] = make_float2(acc[mb][ni][2], acc[mb][ni][3]);
        }
    }
}

// ---------------------------------------------------------------------------
// RoPE: q in place (fp32). k -> g_kh fp16 in m16n8k16 B-frag order:
//   pos(d) = ((d&7)>>1)*16 + (d>>4)*4 + ((d>>3)&1)*2 + (d&1)
// v -> g_vph fp16, paired (rows 2m,2m+1 interleaved as half2).
// ---------------------------------------------------------------------------
__global__ void rope_kernel(float* __restrict__ qkv, __half* __restrict__ kh,
                            __half* __restrict__ vph) {
    int idx = blockIdx.x * blockDim.x + threadIdx.x;
    if (idx >= TOKENS * NH * 32) return;
    int i     = idx & 31;
    int h     = (idx >> 5) & 15;
    int token = idx >> 9;
    int s     = token & (S_LEN - 1);
    int bh    = ((token >> 11) << 4) | h;

    double invf_d = exp(-((double)i / 32.0) * log(10000.0));
    float  invf   = (float)invf_d;
    float  ang    = (float)s * invf;
    float  c = cosf(ang), sn = sinf(ang);

    size_t base = (size_t)token * (3 * HDIM) + h * 64;
    float q1 = qkv[base + i], q2 = qkv[base + i + 32];
    qkv[base + i]      = q1 * c - q2 * sn;
    qkv[base + i + 32] = q2 * c + q1 * sn;

    float k1 = qkv[base + HDIM + i], k2 = qkv[base + HDIM + i + 32];
    float kr1 = k1 * c - k2 * sn, kr2 = k2 * c + k1 * sn;
    __half* kdst = kh + ((size_t)bh * S_LEN + s) * 64;
    int d0 = i, d1 = i + 32;
    #pragma unroll
    for (int e = 0; e < 2; e++) {
        int d = e ? d1 : d0;
        float v = e ? kr2 : kr1;
        int pos = ((d & 7) >> 1) * 16 + (d >> 4) * 4 + ((d >> 3) & 1) * 2 + (d & 1);
        kdst[pos] = __float2half_rn(v);
    }

    size_t vb = ((size_t)bh * 1024 + (s >> 1)) * 64;
    float v1 = qkv[base + 2 * HDIM + i], v2 = qkv[base + 2 * HDIM + i + 32];
    vph[(vb + d0) * 2 + (s & 1)] = __float2half_rn(v1);
    vph[(vb + d1) * 2 + (s & 1)] = __float2half_rn(v2);
}

// ---------------------------------------------------------------------------
// Flash attention: fp16 QK + fp16 PV, causal, fixed-shift base-2 softmax via
// MUFU ex2, row-sum via ones-column MMA (no FADD reduction, no shuffles).
// Block = 128 q-rows of one (b,h); 4 warps x 32 rows. Writes att as fp16.
// ---------------------------------------------------------------------------
#define KH  72              // K row stride (halves)
#define VST 68              // V row stride (half2 words)
__global__ void __launch_bounds__(128, 2) flash2(const float* __restrict__ qkv,
                                                 const __half* __restrict__ kh,
                                                 const __half2* __restrict__ vp,
                                                 __half* __restrict__ outh) {
    extern __shared__ float sm[];
    __half*  KsB = (__half*)sm;                         // [2][64][KH] halves
    __half2* VsB = (__half2*)(sm + (2 * 64 * KH) / 2);  // [2][32][VST] half2

    const int tid = threadIdx.x, lane = tid & 31, w = tid >> 5;
    const int g   = lane >> 2, q = lane & 3;
    const int qb  = gridDim.x - 1 - blockIdx.x;
    const int bh  = blockIdx.y;
    const int b   = bh >> 4, h = bh & 15;
    const int r0  = qb * 128 + w * 32;

    // ---- Q fp16 A-fragments, scaled by (1/8)*log2(e)
    const float SC = 0.125f * 1.44269504088896340736f;
    unsigned qa[2][4][4];
    #pragma unroll
    for (int mi = 0; mi < 2; mi++) {
        const float* rl = qkv + (size_t)(b * S_LEN + r0 + mi * 16 + g) * 3072 + h * 64;
        const float* rh = rl + (size_t)8 * 3072;
        #pragma unroll
        for (int kg = 0; kg < 4; kg++) {
            float2 lo0 = *(const float2*)(rl + kg * 16 + 2 * q);
            float2 hi0 = *(const float2*)(rh + kg * 16 + 2 * q);
            float2 lo8 = *(const float2*)(rl + kg * 16 + 8 + 2 * q);
            float2 hi8 = *(const float2*)(rh + kg * 16 + 8 + 2 * q);
            qa[mi][kg][0] = pkh2(lo0.y * SC, lo0.x * SC);
            qa[mi][kg][1] = pkh2(hi0.y * SC, hi0.x * SC);
            qa[mi][kg][2] = pkh2(lo8.y * SC, lo8.x * SC);
            qa[mi][kg][3] = pkh2(hi8.y * SC, hi8.x * SC);
        }
    }

    float acc[2][8][4] = {};
    float accl[2][4] = {};                       // row sums via ones-MMA
    const unsigned ONES[2] = { 0x3C003C00u, 0x3C003C00u };

    const __half*  Kpl = kh + (size_t)bh * S_LEN * 64;
    const __half2* Vpl = vp + (size_t)bh * 1024 * 64;

    const int kR = tid >> 3, kC = (tid & 7) * 8;
    const int vR = tid >> 2, vC = (tid & 3) * 16;
    const int jmax = 2 * qb + 1;

    {
        #pragma unroll
        for (int i = 0; i < 4; i++)
            cpa16(KsB + (kR + i * 16) * KH + kC, Kpl + (size_t)(kR + i * 16) * 64 + kC);
        #pragma unroll
        for (int i = 0; i < 4; i++)
            cpa16(VsB + vR * VST + vC + 4 * i, Vpl + (size_t)vR * 64 + vC + 4 * i);
    }
    cp_commit();

    for (int jb = 0; jb <= jmax; jb++) {
        cp_wait0();
        __syncthreads();

        if (jb < jmax) {
            const int nb = (jb + 1) & 1;
            const __half*  ks = Kpl + (size_t)((jb + 1) * 64) * 64;
            const __half2* vs = Vpl + (size_t)((jb + 1) * 32 + vR) * 64 + vC;
            #pragma unroll
            for (int i = 0; i < 4; i++)
                cpa16(KsB + (nb * 64 + kR + i * 16) * KH + kC, ks + (size_t)(kR + i * 16) * 64 + kC);
            #pragma unroll
            for (int i = 0; i < 4; i++)
                cpa16(VsB + (nb * 32 + vR) * VST + vC + 4 * i, vs + 4 * i);
            cp_commit();
        }

        if (r0 + 31 >= jb * 64) {
            const __half*  K = KsB + (jb & 1) * 64 * KH;
            const __half2* V = VsB + (jb & 1) * 32 * VST;

            // ---- S = Q @ K^T
            float p[2][8][4];
            #pragma unroll
            for (int n = 0; n < 8; n++) {
                float s0[4] = {}, s1[4] = {};
                const uint4* krow = (const uint4*)(K + (n * 8 + g) * KH + q * 16);
                uint4 k0 = krow[0];
                uint4 k1 = krow[1];
                unsigned b0[2] = { k0.x, k0.y }, b1[2] = { k0.z, k0.w };
                unsigned b2[2] = { k1.x, k1.y }, b3[2] = { k1.z, k1.w };
                hmma16(s0, qa[0][0], b0); hmma16(s0, qa[0][1], b1);
                hmma16(s0, qa[0][2], b2); hmma16(s0, qa[0][3], b3);
                hmma16(s1, qa[1][0], b0); hmma16(s1, qa[1][1], b1);
                hmma16(s1, qa[1][2], b2); hmma16(s1, qa[1][3], b3);
                #pragma unroll
                for (int e = 0; e < 4; e++) { p[0][n][e] = s0[e]; p[1][n][e] = s1[e]; }
            }

            // ---- causal mask
            if (jb * 64 + 63 > r0) {
                #pragma unroll
                for (int mi = 0; mi < 2; mi++) {
                    const int rL = r0 + mi * 16 + g, rH = rL + 8;
                    #pragma unroll
                    for (int n = 0; n < 8; n++) {
                        const int c0 = jb * 64 + n * 8 + 2 * q;
                        if (c0 > rL)     p[mi][n][0] = -1e30f;
                        if (c0 + 1 > rL) p[mi][n][1] = -1e30f;
                        if (c0 > rH)     p[mi][n][2] = -1e30f;
                        if (c0 + 1 > rH) p[mi][n][3] = -1e30f;
                    }
                }
            }

            // ---- p = 2^s via MUFU
            #pragma unroll
            for (int mi = 0; mi < 2; mi++)
                #pragma unroll
                for (int n = 0; n < 8; n++) {
                    p[mi][n][0] = ex2(p[mi][n][0]);
                    p[mi][n][1] = ex2(p[mi][n][1]);
                    p[mi][n][2] = ex2(p[mi][n][2]);
                    p[mi][n][3] = ex2(p[mi][n][3]);
                }

            // ---- acc += P @ V ; l += P @ 1
            #pragma unroll
            for (int t = 0; t < 4; t++) {
                unsigned pa[2][4];
                #pragma unroll
                for (int mi = 0; mi < 2; mi++) {
                    pa[mi][0] = pkh2(p[mi][2 * t][1],     p[mi][2 * t][0]);
                    pa[mi][1] = pkh2(p[mi][2 * t][3],     p[mi][2 * t][2]);
                    pa[mi][2] = pkh2(p[mi][2 * t + 1][1], p[mi][2 * t + 1][0]);
                    pa[mi][3] = pkh2(p[mi][2 * t + 1][3], p[mi][2 * t + 1][2]);
                }
                hmma16(accl[0], pa[0], ONES);
                hmma16(accl[1], pa[1], ONES);
                #pragma unroll
                for (int n = 0; n < 8; n++) {
                    unsigned vb[2] = {
                        *(const unsigned*)&V[(t * 8 + q) * VST + n * 8 + g],
                        *(const unsigned*)&V[(t * 8 + q + 4) * VST + n * 8 + g] };
                    hmma16(acc[0][n], pa[0], vb);
                    hmma16(acc[1][n], pa[1], vb);
                }
            }
        }
    }

    // ---- normalize + write fp16 att (l already cross-quad complete via MMA)
    #pragma unroll
    for (int mi = 0; mi < 2; mi++) {
        const float inv0 = 1.f / accl[mi][0], inv1 = 1.f / accl[mi][2];
        const size_t tokL = (size_t)(b * S_LEN + r0 + mi * 16 + g);
        const size_t tokH = tokL + 8;
        #pragma unroll
        for (int n = 0; n < 8; n++) {
            const int c = h * 64 + n * 8 + 2 * q;
            *(unsigned*)&outh[tokL * HDIM + c] = pkh2(acc[mi][n][1] * inv0, acc[mi][n][0] * inv0);
            *(unsigned*)&outh[tokH * HDIM + c] = pkh2(acc[mi][n][3] * inv1, acc[mi][n][2] * inv1);
        }
    }
}

// ---------------------------------------------------------------------------
// Launch
// ---------------------------------------------------------------------------
extern "C" void kernel_launch(void* const* d_in, const int* in_sizes, int n_in,
                              void* d_out, int out_size) {
    const float* x     = (const float*)d_in[0];
    const float* w_qkv = (const float*)d_in[1];
    const float* w_o   = (const float*)d_in[2];
    float* out = (float*)d_out;

    float* qkv; __half *xh, *wqh, *woh, *ath, *khp, *vph;
    cudaGetSymbolAddress((void**)&qkv, g_qkv);
    cudaGetSymbolAddress((void**)&xh,  g_xh);
    cudaGetSymbolAddress((void**)&wqh, g_wqh);
    cudaGetSymbolAddress((void**)&woh, g_woh);
    cudaGetSymbolAddress((void**)&ath, g_ath);
    cudaGetSymbolAddress((void**)&khp, g_kh);
    cudaGetSymbolAddress((void**)&vph, g_vph);

    // 0) fp16 conversions
    cvt_h<<<(TOKENS * HDIM / 4 + 255) / 256, 256>>>(x, xh, TOKENS * HDIM / 4);
    cvt_h<<<(3 * HDIM * HDIM / 4 + 255) / 256, 256>>>(w_qkv, wqh, 3 * HDIM * HDIM / 4);
    cvt_h<<<(HDIM * HDIM / 4 + 255) / 256, 256>>>(w_o, woh, HDIM * HDIM / 4);

    // 1) QKV projection (fp16 tensor cores)
    cudaFuncSetAttribute(gemm_h_nt, cudaFuncAttributeMaxDynamicSharedMemorySize, 65536);
    gemm_h_nt<<<dim3(3 * HDIM / 128, TOKENS / 128), 128, 65536>>>(xh, wqh, qkv, TOKENS, 3 * HDIM, HDIM);

    // 2) RoPE + K fp16 frag-reorder + V fp16 pairing
    rope_kernel<<<(TOKENS * NH * 32) / 256, 256>>>(qkv, khp, vph);

    // 3) Causal flash attention (fp16) -> att fp16
    const int flash_smem = 2 * 64 * KH * 2 + 2 * 32 * VST * 4;  // 35840 B
    cudaFuncSetAttribute(flash2, cudaFuncAttributeMaxDynamicSharedMemorySize, flash_smem);
    flash2<<<dim3(S_LEN / 128, 2 * NH), 128, flash_smem>>>(qkv, khp, (const __half2*)vph, ath);

    // 4) Output projection (fp16 tensor cores)
    gemm_h_nt<<<dim3(HDIM / 128, TOKENS / 128), 128, 65536>>>(ath, woh, out, TOKENS, HDIM, HDIM);
}

// round 10
// speedup vs baseline: 6.9916x; 1.4366x over previous
#include <cuda_runtime.h>
#include <cuda_fp16.h>
#include <math.h>

#define TOKENS 4096      // B*S = 2*2048
#define S_LEN  2048
#define HDIM   1024
#define NH     16

// Scratch (static device globals — no allocations allowed)
__device__ __align__(256) float  g_qkv[(size_t)TOKENS * 3 * HDIM]; // [token][3*1024]
__device__ __align__(256) __half g_xh [(size_t)TOKENS * HDIM];     // x in fp16
__device__ __align__(256) __half g_wqh[(size_t)3 * HDIM * HDIM];   // w_qkv fp16
__device__ __align__(256) __half g_woh[(size_t)HDIM * HDIM];       // w_o fp16
__device__ __align__(256) __half g_ath[(size_t)TOKENS * HDIM];     // att fp16
__device__ __align__(256) __half g_kh [(size_t)32 * S_LEN * 64];   // K fp16 frag-ordered
__device__ __align__(256) __half g_vph[(size_t)32 * 1024 * 64 * 2]; // V half2 pairs

// ---------------------------------------------------------------------------
// Helpers
// ---------------------------------------------------------------------------
__device__ __forceinline__ void hmma16(float* c, const unsigned* a, const unsigned* b) {
    asm("mma.sync.aligned.m16n8k16.row.col.f32.f16.f16.f32 "
        "{%0,%1,%2,%3}, {%4,%5,%6,%7}, {%8,%9}, {%0,%1,%2,%3};"
        : "+f"(c[0]), "+f"(c[1]), "+f"(c[2]), "+f"(c[3])
        : "r"(a[0]), "r"(a[1]), "r"(a[2]), "r"(a[3]), "r"(b[0]), "r"(b[1]));
}
__device__ __forceinline__ unsigned pkh2(float hi, float lo) {
    unsigned d; asm("cvt.rn.f16x2.f32 %0, %1, %2;" : "=r"(d) : "f"(hi), "f"(lo)); return d;
}
__device__ __forceinline__ float ex2(float x) {
    float y; asm("ex2.approx.f32 %0, %1;" : "=f"(y) : "f"(x)); return y;
}
__device__ __forceinline__ void cpa16(void* s, const void* g) {
    unsigned sa = (unsigned)__cvta_generic_to_shared(s);
    asm volatile("cp.async.cg.shared.global [%0], [%1], 16;" :: "r"(sa), "l"(g));
}
__device__ __forceinline__ void cp_commit() { asm volatile("cp.async.commit_group;"); }
__device__ __forceinline__ void cp_wait0()  { asm volatile("cp.async.wait_group 0;"); }
__device__ __forceinline__ void ldmx4(unsigned* r, unsigned addr) {
    asm volatile("ldmatrix.sync.aligned.m8n8.x4.shared.b16 {%0,%1,%2,%3}, [%4];"
        : "=r"(r[0]), "=r"(r[1]), "=r"(r[2]), "=r"(r[3]) : "r"(addr));
}

// ---------------------------------------------------------------------------
// fp32 -> fp16 convert (pre-pass)
// ---------------------------------------------------------------------------
__global__ void cvt_h(const float* __restrict__ s, __half* __restrict__ d, int n4) {
    int i = blockIdx.x * blockDim.x + threadIdx.x;
    if (i >= n4) return;
    float4 v = ((const float4*)s)[i];
    ((uint2*)d)[i] = make_uint2(pkh2(v.y, v.x), pkh2(v.w, v.z));
}

// ---------------------------------------------------------------------------
// fp16 GEMM: C[M,N] = A[M,K] @ B[N,K]^T (f32 accum/out). 128x128 block tile,
// BK=64 halves, 4 warps (2x2), warp 64x64. cp.async double-buffered smem;
// COALESCED loads: 8 threads cover one 128B row (fix for round-9 L2 blowup).
// XOR-swizzled rows (8x16B groups, grp^row&7) -> conflict-free ldmatrix.x4.
// ---------------------------------------------------------------------------
__global__ void __launch_bounds__(128, 2) gemm_h_nt(
        const __half* __restrict__ A, const __half* __restrict__ B,
        float* __restrict__ C, int M, int N, int K) {
    extern __shared__ char smx[];   // [2][A 16KB | B 16KB]
    const int tid = threadIdx.x, lane = tid & 31;
    const int w   = tid >> 5, wm = w >> 1, wn = w & 1;
    const int g   = lane >> 2, q = lane & 3;

    // coalesced loader mapping: 8 threads per 64-half row
    const int lr = tid >> 3, lc = tid & 7;            // base row 0..15, chunk 0..7
    const __half* Ab = A + (size_t)(blockIdx.y * 128) * K + lc * 8;
    const __half* Bb = B + (size_t)(blockIdx.x * 128) * K + lc * 8;
    const unsigned sbase = (unsigned)__cvta_generic_to_shared(smx);

    // ldmatrix per-lane row bases (row&7 == lane&7 for both A and B)
    const int lrow = ((lane >> 3) & 1) * 8 + (lane & 7);
    const unsigned rbA = sbase + (unsigned)(wm * 64 + lrow) * 128;
    const unsigned rbB = sbase + 16384u + (unsigned)(wn * 64 + lrow) * 128;
    const int gsel = lane >> 4;           // 0/1: lo/hi 16B group of the kg pair
    const int r7   = lane & 7;

    float acc[4][8][4] = {};

    // prefetch stage 0
    {
        char* As = smx; char* Bs = smx + 16384;
        #pragma unroll
        for (int i = 0; i < 8; i++) {
            const int r = lr + i * 16;
            const unsigned doff = (unsigned)(r * 128 + ((lc ^ (r & 7)) * 16));
            cpa16(As + doff, Ab + (size_t)r * K);
            cpa16(Bs + doff, Bb + (size_t)r * K);
        }
    }
    cp_commit();

    const int nS = K >> 6;               // 16 stages
    for (int s = 0; s < nS; s++) {
        cp_wait0();
        __syncthreads();

        if (s + 1 < nS) {
            char* As = smx + ((s + 1) & 1) * 32768;
            char* Bs = As + 16384;
            const __half* a = Ab + (s + 1) * 64;
            const __half* b = Bb + (s + 1) * 64;
            #pragma unroll
            for (int i = 0; i < 8; i++) {
                const int r = lr + i * 16;
                const unsigned doff = (unsigned)(r * 128 + ((lc ^ (r & 7)) * 16));
                cpa16(As + doff, a + (size_t)r * K);
                cpa16(Bs + doff, b + (size_t)r * K);
            }
            cp_commit();
        }

        const unsigned so = (unsigned)((s & 1) * 32768);
        #pragma unroll
        for (int kgi = 0; kgi < 4; kgi++) {
            const unsigned xo = (unsigned)((((kgi << 1) | gsel) ^ r7) * 16);
            unsigned af[4][4], bf[4][4];
            #pragma unroll
            for (int mb = 0; mb < 4; mb++) ldmx4(af[mb], rbA + so + mb * 2048 + xo);
            #pragma unroll
            for (int np = 0; np < 4; np++) ldmx4(bf[np], rbB + so + np * 2048 + xo);
            #pragma unroll
            for (int mb = 0; mb < 4; mb++)
                #pragma unroll
                for (int ni = 0; ni < 8; ni++) {
                    unsigned bb[2] = { bf[ni >> 1][ni & 1], bf[ni >> 1][(ni & 1) + 2] };
                    hmma16(acc[mb][ni], af[mb], bb);
                }
        }
        __syncthreads();
    }

    #pragma unroll
    for (int mb = 0; mb < 4; mb++) {
        const int row = blockIdx.y * 128 + wm * 64 + mb * 16 + g;
        #pragma unroll
        for (int ni = 0; ni < 8; ni++) {
            const int col = blockIdx.x * 128 + wn * 64 + ni * 8 + 2 * q;
            *(float2*)&C[(size_t)row * N + col]       = make_float2(acc[mb][ni][0], acc[mb][ni][1]);
            *(float2*)&C[(size_t)(row + 8) * N + col] = make_float2(acc[mb][ni][2], acc[mb][ni][3]);
        }
    }
}

// ---------------------------------------------------------------------------
// RoPE: q in place (fp32). k -> g_kh fp16 in m16n8k16 B-frag order:
//   pos(d) = ((d&7)>>1)*16 + (d>>4)*4 + ((d>>3)&1)*2 + (d&1)
// v -> g_vph fp16, paired (rows 2m,2m+1 interleaved as half2).
// ---------------------------------------------------------------------------
__global__ void rope_kernel(float* __restrict__ qkv, __half* __restrict__ kh,
                            __half* __restrict__ vph) {
    int idx = blockIdx.x * blockDim.x + threadIdx.x;
    if (idx >= TOKENS * NH * 32) return;
    int i     = idx & 31;
    int h     = (idx >> 5) & 15;
    int token = idx >> 9;
    int s     = token & (S_LEN - 1);
    int bh    = ((token >> 11) << 4) | h;

    double invf_d = exp(-((double)i / 32.0) * log(10000.0));
    float  invf   = (float)invf_d;
    float  ang    = (float)s * invf;
    float  c = cosf(ang), sn = sinf(ang);

    size_t base = (size_t)token * (3 * HDIM) + h * 64;
    float q1 = qkv[base + i], q2 = qkv[base + i + 32];
    qkv[base + i]      = q1 * c - q2 * sn;
    qkv[base + i + 32] = q2 * c + q1 * sn;

    float k1 = qkv[base + HDIM + i], k2 = qkv[base + HDIM + i + 32];
    float kr1 = k1 * c - k2 * sn, kr2 = k2 * c + k1 * sn;
    __half* kdst = kh + ((size_t)bh * S_LEN + s) * 64;
    int d0 = i, d1 = i + 32;
    #pragma unroll
    for (int e = 0; e < 2; e++) {
        int d = e ? d1 : d0;
        float v = e ? kr2 : kr1;
        int pos = ((d & 7) >> 1) * 16 + (d >> 4) * 4 + ((d >> 3) & 1) * 2 + (d & 1);
        kdst[pos] = __float2half_rn(v);
    }

    size_t vb = ((size_t)bh * 1024 + (s >> 1)) * 64;
    float v1 = qkv[base + 2 * HDIM + i], v2 = qkv[base + 2 * HDIM + i + 32];
    vph[(vb + d0) * 2 + (s & 1)] = __float2half_rn(v1);
    vph[(vb + d1) * 2 + (s & 1)] = __float2half_rn(v2);
}

// ---------------------------------------------------------------------------
// Flash attention: fp16 QK + fp16 PV, causal, fixed-shift base-2 softmax via
// MUFU ex2, row-sum via ones-column MMA. Block = 128 q-rows of one (b,h);
// 4 warps x 32 rows. Writes att as fp16.
// ---------------------------------------------------------------------------
#define KH  72              // K row stride (halves)
#define VST 68              // V row stride (half2 words)
__global__ void __launch_bounds__(128, 2) flash2(const float* __restrict__ qkv,
                                                 const __half* __restrict__ kh,
                                                 const __half2* __restrict__ vp,
                                                 __half* __restrict__ outh) {
    extern __shared__ float sm[];
    __half*  KsB = (__half*)sm;                         // [2][64][KH] halves
    __half2* VsB = (__half2*)(sm + (2 * 64 * KH) / 2);  // [2][32][VST] half2

    const int tid = threadIdx.x, lane = tid & 31, w = tid >> 5;
    const int g   = lane >> 2, q = lane & 3;
    const int qb  = gridDim.x - 1 - blockIdx.x;
    const int bh  = blockIdx.y;
    const int b   = bh >> 4, h = bh & 15;
    const int r0  = qb * 128 + w * 32;

    // ---- Q fp16 A-fragments, scaled by (1/8)*log2(e)
    const float SC = 0.125f * 1.44269504088896340736f;
    unsigned qa[2][4][4];
    #pragma unroll
    for (int mi = 0; mi < 2; mi++) {
        const float* rl = qkv + (size_t)(b * S_LEN + r0 + mi * 16 + g) * 3072 + h * 64;
        const float* rh = rl + (size_t)8 * 3072;
        #pragma unroll
        for (int kg = 0; kg < 4; kg++) {
            float2 lo0 = *(const float2*)(rl + kg * 16 + 2 * q);
            float2 hi0 = *(const float2*)(rh + kg * 16 + 2 * q);
            float2 lo8 = *(const float2*)(rl + kg * 16 + 8 + 2 * q);
            float2 hi8 = *(const float2*)(rh + kg * 16 + 8 + 2 * q);
            qa[mi][kg][0] = pkh2(lo0.y * SC, lo0.x * SC);
            qa[mi][kg][1] = pkh2(hi0.y * SC, hi0.x * SC);
            qa[mi][kg][2] = pkh2(lo8.y * SC, lo8.x * SC);
            qa[mi][kg][3] = pkh2(hi8.y * SC, hi8.x * SC);
        }
    }

    float acc[2][8][4] = {};
    float accl[2][4] = {};                       // row sums via ones-MMA
    const unsigned ONES[2] = { 0x3C003C00u, 0x3C003C00u };

    const __half*  Kpl = kh + (size_t)bh * S_LEN * 64;
    const __half2* Vpl = vp + (size_t)bh * 1024 * 64;

    const int kR = tid >> 3, kC = (tid & 7) * 8;
    const int vR = tid >> 2, vC = (tid & 3) * 16;
    const int jmax = 2 * qb + 1;

    {
        #pragma unroll
        for (int i = 0; i < 4; i++)
            cpa16(KsB + (kR + i * 16) * KH + kC, Kpl + (size_t)(kR + i * 16) * 64 + kC);
        #pragma unroll
        for (int i = 0; i < 4; i++)
            cpa16(VsB + vR * VST + vC + 4 * i, Vpl + (size_t)vR * 64 + vC + 4 * i);
    }
    cp_commit();

    for (int jb = 0; jb <= jmax; jb++) {
        cp_wait0();
        __syncthreads();

        if (jb < jmax) {
            const int nb = (jb + 1) & 1;
            const __half*  ks = Kpl + (size_t)((jb + 1) * 64) * 64;
            const __half2* vs = Vpl + (size_t)((jb + 1) * 32 + vR) * 64 + vC;
            #pragma unroll
            for (int i = 0; i < 4; i++)
                cpa16(KsB + (nb * 64 + kR + i * 16) * KH + kC, ks + (size_t)(kR + i * 16) * 64 + kC);
            #pragma unroll
            for (int i = 0; i < 4; i++)
                cpa16(VsB + (nb * 32 + vR) * VST + vC + 4 * i, vs + 4 * i);
            cp_commit();
        }

        if (r0 + 31 >= jb * 64) {
            const __half*  K = KsB + (jb & 1) * 64 * KH;
            const __half2* V = VsB + (jb & 1) * 32 * VST;

            // ---- S = Q @ K^T
            float p[2][8][4];
            #pragma unroll
            for (int n = 0; n < 8; n++) {
                float s0[4] = {}, s1[4] = {};
                const uint4* krow = (const uint4*)(K + (n * 8 + g) * KH + q * 16);
                uint4 k0 = krow[0];
                uint4 k1 = krow[1];
                unsigned b0[2] = { k0.x, k0.y }, b1[2] = { k0.z, k0.w };
                unsigned b2[2] = { k1.x, k1.y }, b3[2] = { k1.z, k1.w };
                hmma16(s0, qa[0][0], b0); hmma16(s0, qa[0][1], b1);
                hmma16(s0, qa[0][2], b2); hmma16(s0, qa[0][3], b3);
                hmma16(s1, qa[1][0], b0); hmma16(s1, qa[1][1], b1);
                hmma16(s1, qa[1][2], b2); hmma16(s1, qa[1][3], b3);
                #pragma unroll
                for (int e = 0; e < 4; e++) { p[0][n][e] = s0[e]; p[1][n][e] = s1[e]; }
            }

            // ---- causal mask
            if (jb * 64 + 63 > r0) {
                #pragma unroll
                for (int mi = 0; mi < 2; mi++) {
                    const int rL = r0 + mi * 16 + g, rH = rL + 8;
                    #pragma unroll
                    for (int n = 0; n < 8; n++) {
                        const int c0 = jb * 64 + n * 8 + 2 * q;
                        if (c0 > rL)     p[mi][n][0] = -1e30f;
                        if (c0 + 1 > rL) p[mi][n][1] = -1e30f;
                        if (c0 > rH)     p[mi][n][2] = -1e30f;
                        if (c0 + 1 > rH) p[mi][n][3] = -1e30f;
                    }
                }
            }

            // ---- p = 2^s via MUFU
            #pragma unroll
            for (int mi = 0; mi < 2; mi++)
                #pragma unroll
                for (int n = 0; n < 8; n++) {
                    p[mi][n][0] = ex2(p[mi][n][0]);
                    p[mi][n][1] = ex2(p[mi][n][1]);
                    p[mi][n][2] = ex2(p[mi][n][2]);
                    p[mi][n][3] = ex2(p[mi][n][3]);
                }

            // ---- acc += P @ V ; l += P @ 1
            #pragma unroll
            for (int t = 0; t < 4; t++) {
                unsigned pa[2][4];
                #pragma unroll
                for (int mi = 0; mi < 2; mi++) {
                    pa[mi][0] = pkh2(p[mi][2 * t][1],     p[mi][2 * t][0]);
                    pa[mi][1] = pkh2(p[mi][2 * t][3],     p[mi][2 * t][2]);
                    pa[mi][2] = pkh2(p[mi][2 * t + 1][1], p[mi][2 * t + 1][0]);
                    pa[mi][3] = pkh2(p[mi][2 * t + 1][3], p[mi][2 * t + 1][2]);
                }
                hmma16(accl[0], pa[0], ONES);
                hmma16(accl[1], pa[1], ONES);
                #pragma unroll
                for (int n = 0; n < 8; n++) {
                    unsigned vb[2] = {
                        *(const unsigned*)&V[(t * 8 + q) * VST + n * 8 + g],
                        *(const unsigned*)&V[(t * 8 + q + 4) * VST + n * 8 + g] };
                    hmma16(acc[0][n], pa[0], vb);
                    hmma16(acc[1][n], pa[1], vb);
                }
            }
        }
    }

    // ---- normalize + write fp16 att (l already cross-quad complete via MMA)
    #pragma unroll
    for (int mi = 0; mi < 2; mi++) {
        const float inv0 = 1.f / accl[mi][0], inv1 = 1.f / accl[mi][2];
        const size_t tokL = (size_t)(b * S_LEN + r0 + mi * 16 + g);
        const size_t tokH = tokL + 8;
        #pragma unroll
        for (int n = 0; n < 8; n++) {
            const int c = h * 64 + n * 8 + 2 * q;
            *(unsigned*)&outh[tokL * HDIM + c] = pkh2(acc[mi][n][1] * inv0, acc[mi][n][0] * inv0);
            *(unsigned*)&outh[tokH * HDIM + c] = pkh2(acc[mi][n][3] * inv1, acc[mi][n][2] * inv1);
        }
    }
}

// ---------------------------------------------------------------------------
// Launch
// ---------------------------------------------------------------------------
extern "C" void kernel_launch(void* const* d_in, const int* in_sizes, int n_in,
                              void* d_out, int out_size) {
    const float* x     = (const float*)d_in[0];
    const float* w_qkv = (const float*)d_in[1];
    const float* w_o   = (const float*)d_in[2];
    float* out = (float*)d_out;

    float* qkv; __half *xh, *wqh, *woh, *ath, *khp, *vph;
    cudaGetSymbolAddress((void**)&qkv, g_qkv);
    cudaGetSymbolAddress((void**)&xh,  g_xh);
    cudaGetSymbolAddress((void**)&wqh, g_wqh);
    cudaGetSymbolAddress((void**)&woh, g_woh);
    cudaGetSymbolAddress((void**)&ath, g_ath);
    cudaGetSymbolAddress((void**)&khp, g_kh);
    cudaGetSymbolAddress((void**)&vph, g_vph);

    // 0) fp16 conversions
    cvt_h<<<(TOKENS * HDIM / 4 + 255) / 256, 256>>>(x, xh, TOKENS * HDIM / 4);
    cvt_h<<<(3 * HDIM * HDIM / 4 + 255) / 256, 256>>>(w_qkv, wqh, 3 * HDIM * HDIM / 4);
    cvt_h<<<(HDIM * HDIM / 4 + 255) / 256, 256>>>(w_o, woh, HDIM * HDIM / 4);

    // 1) QKV projection (fp16 tensor cores, coalesced loads)
    cudaFuncSetAttribute(gemm_h_nt, cudaFuncAttributeMaxDynamicSharedMemorySize, 65536);
    gemm_h_nt<<<dim3(3 * HDIM / 128, TOKENS / 128), 128, 65536>>>(xh, wqh, qkv, TOKENS, 3 * HDIM, HDIM);

    // 2) RoPE + K fp16 frag-reorder + V fp16 pairing
    rope_kernel<<<(TOKENS * NH * 32) / 256, 256>>>(qkv, khp, vph);

    // 3) Causal flash attention (fp16) -> att fp16
    const int flash_smem = 2 * 64 * KH * 2 + 2 * 32 * VST * 4;  // 35840 B
    cudaFuncSetAttribute(flash2, cudaFuncAttributeMaxDynamicSharedMemorySize, flash_smem);
    flash2<<<dim3(S_LEN / 128, 2 * NH), 128, flash_smem>>>(qkv, khp, (const __half2*)vph, ath);

    // 4) Output projection (fp16 tensor cores)
    gemm_h_nt<<<dim3(HDIM / 128, TOKENS / 128), 128, 65536>>>(ath, woh, out, TOKENS, HDIM, HDIM);
}

// round 11
// speedup vs baseline: 7.0926x; 1.0145x over previous
#include <cuda_runtime.h>
#include <cuda_fp16.h>
#include <math.h>

#define TOKENS 4096      // B*S = 2*2048
#define S_LEN  2048
#define HDIM   1024
#define NH     16

// Scratch (static device globals — no allocations allowed)
__device__ __align__(256) float  g_qkv[(size_t)TOKENS * 3 * HDIM]; // [token][3*1024]
__device__ __align__(256) __half g_xh [(size_t)TOKENS * HDIM];     // x in fp16
__device__ __align__(256) __half g_wqh[(size_t)3 * HDIM * HDIM];   // w_qkv fp16
__device__ __align__(256) __half g_woh[(size_t)HDIM * HDIM];       // w_o fp16
__device__ __align__(256) __half g_ath[(size_t)TOKENS * HDIM];     // att fp16
__device__ __align__(256) __half g_kh [(size_t)32 * S_LEN * 64];   // K fp16 frag-ordered
__device__ __align__(256) __half g_vph[(size_t)32 * 1024 * 64 * 2]; // V half2 pairs

// ---------------------------------------------------------------------------
// Helpers
// ---------------------------------------------------------------------------
__device__ __forceinline__ void hmma16(float* c, const unsigned* a, const unsigned* b) {
    asm("mma.sync.aligned.m16n8k16.row.col.f32.f16.f16.f32 "
        "{%0,%1,%2,%3}, {%4,%5,%6,%7}, {%8,%9}, {%0,%1,%2,%3};"
        : "+f"(c[0]), "+f"(c[1]), "+f"(c[2]), "+f"(c[3])
        : "r"(a[0]), "r"(a[1]), "r"(a[2]), "r"(a[3]), "r"(b[0]), "r"(b[1]));
}
__device__ __forceinline__ unsigned pkh2(float hi, float lo) {
    unsigned d; asm("cvt.rn.f16x2.f32 %0, %1, %2;" : "=r"(d) : "f"(hi), "f"(lo)); return d;
}
// MUFU exp2 on packed fp16x2 (both halves in one op)
__device__ __forceinline__ unsigned hex2(unsigned x) {
    unsigned y; asm("ex2.approx.f16x2 %0, %1;" : "=r"(y) : "r"(x)); return y;
}
__device__ __forceinline__ void cpa16(void* s, const void* g) {
    unsigned sa = (unsigned)__cvta_generic_to_shared(s);
    asm volatile("cp.async.cg.shared.global [%0], [%1], 16;" :: "r"(sa), "l"(g));
}
__device__ __forceinline__ void cp_commit() { asm volatile("cp.async.commit_group;"); }
__device__ __forceinline__ void cp_wait0()  { asm volatile("cp.async.wait_group 0;"); }
__device__ __forceinline__ void cp_wait1()  { asm volatile("cp.async.wait_group 1;"); }
__device__ __forceinline__ void ldmx4(unsigned* r, unsigned addr) {
    asm volatile("ldmatrix.sync.aligned.m8n8.x4.shared.b16 {%0,%1,%2,%3}, [%4];"
        : "=r"(r[0]), "=r"(r[1]), "=r"(r[2]), "=r"(r[3]) : "r"(addr));
}

// ---------------------------------------------------------------------------
// fp32 -> fp16 convert (pre-pass)
// ---------------------------------------------------------------------------
__global__ void cvt_h(const float* __restrict__ s, __half* __restrict__ d, int n4) {
    int i = blockIdx.x * blockDim.x + threadIdx.x;
    if (i >= n4) return;
    float4 v = ((const float4*)s)[i];
    ((uint2*)d)[i] = make_uint2(pkh2(v.y, v.x), pkh2(v.w, v.z));
}

// ---------------------------------------------------------------------------
// fp16 GEMM: C[M,N] = A[M,K] @ B[N,K]^T (f32 accum/out). 128x128 block tile,
// BK=64 halves, 4 warps (2x2), warp 64x64. THREE-stage cp.async pipeline
// (wait_group 1 -> two compute phases of latency slack). Coalesced loads:
// 8 threads cover one 128B row. XOR swizzle (grp^row&7) for ldmatrix.x4.
// ---------------------------------------------------------------------------
__global__ void __launch_bounds__(128, 2) gemm_h_nt(
        const __half* __restrict__ A, const __half* __restrict__ B,
        float* __restrict__ C, int M, int N, int K) {
    extern __shared__ char smx[];   // [3][A 16KB | B 16KB]
    const int tid = threadIdx.x, lane = tid & 31;
    const int w   = tid >> 5, wm = w >> 1, wn = w & 1;
    const int g   = lane >> 2, q = lane & 3;

    // coalesced loader mapping: 8 threads per 64-half row
    const int lr = tid >> 3, lc = tid & 7;            // base row 0..15, chunk 0..7
    const __half* Ab = A + (size_t)(blockIdx.y * 128) * K + lc * 8;
    const __half* Bb = B + (size_t)(blockIdx.x * 128) * K + lc * 8;
    const unsigned sbase = (unsigned)__cvta_generic_to_shared(smx);
    const unsigned dbase = (unsigned)(lr * 128 + ((lc ^ (lr & 7)) * 16)); // +i*2048

    // ldmatrix per-lane row bases
    const int lrow = ((lane >> 3) & 1) * 8 + (lane & 7);
    const unsigned rbA = sbase + (unsigned)(wm * 64 + lrow) * 128;
    const unsigned rbB = sbase + 16384u + (unsigned)(wn * 64 + lrow) * 128;
    const int gsel = lane >> 4;
    const int r7   = lane & 7;

    float acc[4][8][4] = {};
    const int nS = K >> 6;               // stages

    // prologue: prefetch stages 0 and 1
    #pragma unroll
    for (int st = 0; st < 2; st++) {
        char* As = smx + st * 32768;
        char* Bs = As + 16384;
        const __half* a = Ab + st * 64;
        const __half* b = Bb + st * 64;
        #pragma unroll
        for (int i = 0; i < 8; i++) {
            cpa16(As + dbase + i * 2048, a + (size_t)(lr + i * 16) * K);
            cpa16(Bs + dbase + i * 2048, b + (size_t)(lr + i * 16) * K);
        }
        cp_commit();
    }

    for (int s = 0; s < nS; s++) {
        cp_wait1();
        __syncthreads();

        if (s + 2 < nS) {   // prefetch stage s+2 into buffer (s+2)%3
            char* As = smx + ((s + 2) % 3) * 32768;
            char* Bs = As + 16384;
            const __half* a = Ab + (s + 2) * 64;
            const __half* b = Bb + (s + 2) * 64;
            #pragma unroll
            for (int i = 0; i < 8; i++) {
                cpa16(As + dbase + i * 2048, a + (size_t)(lr + i * 16) * K);
                cpa16(Bs + dbase + i * 2048, b + (size_t)(lr + i * 16) * K);
            }
        }
        cp_commit();        // always one group per iteration (empty ok)

        const unsigned so = (unsigned)((s % 3) * 32768);
        #pragma unroll
        for (int kgi = 0; kgi < 4; kgi++) {
            const unsigned xo = (unsigned)((((kgi << 1) | gsel) ^ r7) * 16);
            unsigned af[4][4], bf[4][4];
            #pragma unroll
            for (int mb = 0; mb < 4; mb++) ldmx4(af[mb], rbA + so + mb * 2048 + xo);
            #pragma unroll
            for (int np = 0; np < 4; np++) ldmx4(bf[np], rbB + so + np * 2048 + xo);
            #pragma unroll
            for (int mb = 0; mb < 4; mb++)
                #pragma unroll
                for (int ni = 0; ni < 8; ni++) {
                    unsigned bb[2] = { bf[ni >> 1][ni & 1], bf[ni >> 1][(ni & 1) + 2] };
                    hmma16(acc[mb][ni], af[mb], bb);
                }
        }
        __syncthreads();
    }

    #pragma unroll
    for (int mb = 0; mb < 4; mb++) {
        const int row = blockIdx.y * 128 + wm * 64 + mb * 16 + g;
        #pragma unroll
        for (int ni = 0; ni < 8; ni++) {
            const int col = blockIdx.x * 128 + wn * 64 + ni * 8 + 2 * q;
            *(float2*)&C[(size_t)row * N + col]       = make_float2(acc[mb][ni][0], acc[mb][ni][1]);
            *(float2*)&C[(size_t)(row + 8) * N + col] = make_float2(acc[mb][ni][2], acc[mb][ni][3]);
        }
    }
}

// ---------------------------------------------------------------------------
// RoPE: q in place (fp32). k -> g_kh fp16 in m16n8k16 B-frag order:
//   pos(d) = ((d&7)>>1)*16 + (d>>4)*4 + ((d>>3)&1)*2 + (d&1)
// v -> g_vph fp16, paired (rows 2m,2m+1 interleaved as half2).
// ---------------------------------------------------------------------------
__global__ void rope_kernel(float* __restrict__ qkv, __half* __restrict__ kh,
                            __half* __restrict__ vph) {
    int idx = blockIdx.x * blockDim.x + threadIdx.x;
    if (idx >= TOKENS * NH * 32) return;
    int i     = idx & 31;
    int h     = (idx >> 5) & 15;
    int token = idx >> 9;
    int s     = token & (S_LEN - 1);
    int bh    = ((token >> 11) << 4) | h;

    double invf_d = exp(-((double)i / 32.0) * log(10000.0));
    float  invf   = (float)invf_d;
    float  ang    = (float)s * invf;
    float  c = cosf(ang), sn = sinf(ang);

    size_t base = (size_t)token * (3 * HDIM) + h * 64;
    float q1 = qkv[base + i], q2 = qkv[base + i + 32];
    qkv[base + i]      = q1 * c - q2 * sn;
    qkv[base + i + 32] = q2 * c + q1 * sn;

    float k1 = qkv[base + HDIM + i], k2 = qkv[base + HDIM + i + 32];
    float kr1 = k1 * c - k2 * sn, kr2 = k2 * c + k1 * sn;
    __half* kdst = kh + ((size_t)bh * S_LEN + s) * 64;
    int d0 = i, d1 = i + 32;
    #pragma unroll
    for (int e = 0; e < 2; e++) {
        int d = e ? d1 : d0;
        float v = e ? kr2 : kr1;
        int pos = ((d & 7) >> 1) * 16 + (d >> 4) * 4 + ((d >> 3) & 1) * 2 + (d & 1);
        kdst[pos] = __float2half_rn(v);
    }

    size_t vb = ((size_t)bh * 1024 + (s >> 1)) * 64;
    float v1 = qkv[base + 2 * HDIM + i], v2 = qkv[base + 2 * HDIM + i + 32];
    vph[(vb + d0) * 2 + (s & 1)] = __float2half_rn(v1);
    vph[(vb + d1) * 2 + (s & 1)] = __float2half_rn(v2);
}

// ---------------------------------------------------------------------------
// Flash attention: fp16 QK + fp16 PV, causal, fixed-shift base-2 softmax via
// MUFU ex2.f16x2 (packed: half the MUFU issues, outputs ARE the PV A-frags).
// Row-sum via ones-column MMA. V stride 72 -> conflict-free LDS.
// Block = 128 q-rows of one (b,h); 4 warps x 32 rows. Writes att as fp16.
// ---------------------------------------------------------------------------
#define KH  72              // K row stride (halves)
#define VST 72              // V row stride (half2 words): bank = 8q+8n+g, bijective
__global__ void __launch_bounds__(128, 2) flash2(const float* __restrict__ qkv,
                                                 const __half* __restrict__ kh,
                                                 const __half2* __restrict__ vp,
                                                 __half* __restrict__ outh) {
    extern __shared__ float sm[];
    __half*  KsB = (__half*)sm;                         // [2][64][KH] halves
    __half2* VsB = (__half2*)(sm + (2 * 64 * KH) / 2);  // [2][32][VST] half2

    const int tid = threadIdx.x, lane = tid & 31, w = tid >> 5;
    const int g   = lane >> 2, q = lane & 3;
    const int qb  = gridDim.x - 1 - blockIdx.x;
    const int bh  = blockIdx.y;
    const int b   = bh >> 4, h = bh & 15;
    const int r0  = qb * 128 + w * 32;

    // ---- Q fp16 A-fragments, scaled by (1/8)*log2(e)
    const float SC = 0.125f * 1.44269504088896340736f;
    unsigned qa[2][4][4];
    #pragma unroll
    for (int mi = 0; mi < 2; mi++) {
        const float* rl = qkv + (size_t)(b * S_LEN + r0 + mi * 16 + g) * 3072 + h * 64;
        const float* rh = rl + (size_t)8 * 3072;
        #pragma unroll
        for (int kg = 0; kg < 4; kg++) {
            float2 lo0 = *(const float2*)(rl + kg * 16 + 2 * q);
            float2 hi0 = *(const float2*)(rh + kg * 16 + 2 * q);
            float2 lo8 = *(const float2*)(rl + kg * 16 + 8 + 2 * q);
            float2 hi8 = *(const float2*)(rh + kg * 16 + 8 + 2 * q);
            qa[mi][kg][0] = pkh2(lo0.y * SC, lo0.x * SC);
            qa[mi][kg][1] = pkh2(hi0.y * SC, hi0.x * SC);
            qa[mi][kg][2] = pkh2(lo8.y * SC, lo8.x * SC);
            qa[mi][kg][3] = pkh2(hi8.y * SC, hi8.x * SC);
        }
    }

    float acc[2][8][4] = {};
    float accl[2][4] = {};                       // row sums via ones-MMA
    const unsigned ONES[2] = { 0x3C003C00u, 0x3C003C00u };

    const __half*  Kpl = kh + (size_t)bh * S_LEN * 64;
    const __half2* Vpl = vp + (size_t)bh * 1024 * 64;

    const int kR = tid >> 3, kC = (tid & 7) * 8;
    const int vR = tid >> 2, vC = (tid & 3) * 16;
    const int jmax = 2 * qb + 1;

    {
        #pragma unroll
        for (int i = 0; i < 4; i++)
            cpa16(KsB + (kR + i * 16) * KH + kC, Kpl + (size_t)(kR + i * 16) * 64 + kC);
        #pragma unroll
        for (int i = 0; i < 4; i++)
            cpa16(VsB + vR * VST + vC + 4 * i, Vpl + (size_t)vR * 64 + vC + 4 * i);
    }
    cp_commit();

    for (int jb = 0; jb <= jmax; jb++) {
        cp_wait0();
        __syncthreads();

        if (jb < jmax) {
            const int nb = (jb + 1) & 1;
            const __half*  ks = Kpl + (size_t)((jb + 1) * 64) * 64;
            const __half2* vs = Vpl + (size_t)((jb + 1) * 32 + vR) * 64 + vC;
            #pragma unroll
            for (int i = 0; i < 4; i++)
                cpa16(KsB + (nb * 64 + kR + i * 16) * KH + kC, ks + (size_t)(kR + i * 16) * 64 + kC);
            #pragma unroll
            for (int i = 0; i < 4; i++)
                cpa16(VsB + (nb * 32 + vR) * VST + vC + 4 * i, vs + 4 * i);
            cp_commit();
        }

        if (r0 + 31 >= jb * 64) {
            const __half*  K = KsB + (jb & 1) * 64 * KH;
            const __half2* V = VsB + (jb & 1) * 32 * VST;

            // ---- S = Q @ K^T
            float p[2][8][4];
            #pragma unroll
            for (int n = 0; n < 8; n++) {
                float s0[4] = {}, s1[4] = {};
                const uint4* krow = (const uint4*)(K + (n * 8 + g) * KH + q * 16);
                uint4 k0 = krow[0];
                uint4 k1 = krow[1];
                unsigned b0[2] = { k0.x, k0.y }, b1[2] = { k0.z, k0.w };
                unsigned b2[2] = { k1.x, k1.y }, b3[2] = { k1.z, k1.w };
                hmma16(s0, qa[0][0], b0); hmma16(s0, qa[0][1], b1);
                hmma16(s0, qa[0][2], b2); hmma16(s0, qa[0][3], b3);
                hmma16(s1, qa[1][0], b0); hmma16(s1, qa[1][1], b1);
                hmma16(s1, qa[1][2], b2); hmma16(s1, qa[1][3], b3);
                #pragma unroll
                for (int e = 0; e < 4; e++) { p[0][n][e] = s0[e]; p[1][n][e] = s1[e]; }
            }

            // ---- causal mask (fp16 pack of -1e30 -> -inf, ex2 -> 0)
            if (jb * 64 + 63 > r0) {
                #pragma unroll
                for (int mi = 0; mi < 2; mi++) {
                    const int rL = r0 + mi * 16 + g, rH = rL + 8;
                    #pragma unroll
                    for (int n = 0; n < 8; n++) {
                        const int c0 = jb * 64 + n * 8 + 2 * q;
                        if (c0 > rL)     p[mi][n][0] = -1e30f;
                        if (c0 + 1 > rL) p[mi][n][1] = -1e30f;
                        if (c0 > rH)     p[mi][n][2] = -1e30f;
                        if (c0 + 1 > rH) p[mi][n][3] = -1e30f;
                    }
                }
            }

            // ---- p = 2^s: pack scores to fp16x2, MUFU ex2 on pairs.
            // pp[mi][n][0] = {p(k even), p(k odd)} rows g / pp[..][1] rows g+8
            unsigned pp[2][8][2];
            #pragma unroll
            for (int mi = 0; mi < 2; mi++)
                #pragma unroll
                for (int n = 0; n < 8; n++) {
                    pp[mi][n][0] = hex2(pkh2(p[mi][n][1], p[mi][n][0]));
                    pp[mi][n][1] = hex2(pkh2(p[mi][n][3], p[mi][n][2]));
                }

            // ---- acc += P @ V ; l += P @ 1  (pp ARE the A-frags)
            #pragma unroll
            for (int t = 0; t < 4; t++) {
                unsigned pa[2][4];
                #pragma unroll
                for (int mi = 0; mi < 2; mi++) {
                    pa[mi][0] = pp[mi][2 * t][0];
                    pa[mi][1] = pp[mi][2 * t][1];
                    pa[mi][2] = pp[mi][2 * t + 1][0];
                    pa[mi][3] = pp[mi][2 * t + 1][1];
                }
                hmma16(accl[0], pa[0], ONES);
                hmma16(accl[1], pa[1], ONES);
                #pragma unroll
                for (int n = 0; n < 8; n++) {
                    unsigned vb[2] = {
                        *(const unsigned*)&V[(t * 8 + q) * VST + n * 8 + g],
                        *(const unsigned*)&V[(t * 8 + q + 4) * VST + n * 8 + g] };
                    hmma16(acc[0][n], pa[0], vb);
                    hmma16(acc[1][n], pa[1], vb);
                }
            }
        }
    }

    // ---- normalize + write fp16 att (l already cross-quad complete via MMA)
    #pragma unroll
    for (int mi = 0; mi < 2; mi++) {
        const float inv0 = 1.f / accl[mi][0], inv1 = 1.f / accl[mi][2];
        const size_t tokL = (size_t)(b * S_LEN + r0 + mi * 16 + g);
        const size_t tokH = tokL + 8;
        #pragma unroll
        for (int n = 0; n < 8; n++) {
            const int c = h * 64 + n * 8 + 2 * q;
            *(unsigned*)&outh[tokL * HDIM + c] = pkh2(acc[mi][n][1] * inv0, acc[mi][n][0] * inv0);
            *(unsigned*)&outh[tokH * HDIM + c] = pkh2(acc[mi][n][3] * inv1, acc[mi][n][2] * inv1);
        }
    }
}

// ---------------------------------------------------------------------------
// Launch
// ---------------------------------------------------------------------------
extern "C" void kernel_launch(void* const* d_in, const int* in_sizes, int n_in,
                              void* d_out, int out_size) {
    const float* x     = (const float*)d_in[0];
    const float* w_qkv = (const float*)d_in[1];
    const float* w_o   = (const float*)d_in[2];
    float* out = (float*)d_out;

    float* qkv; __half *xh, *wqh, *woh, *ath, *khp, *vph;
    cudaGetSymbolAddress((void**)&qkv, g_qkv);
    cudaGetSymbolAddress((void**)&xh,  g_xh);
    cudaGetSymbolAddress((void**)&wqh, g_wqh);
    cudaGetSymbolAddress((void**)&woh, g_woh);
    cudaGetSymbolAddress((void**)&ath, g_ath);
    cudaGetSymbolAddress((void**)&khp, g_kh);
    cudaGetSymbolAddress((void**)&vph, g_vph);

    // 0) fp16 conversions
    cvt_h<<<(TOKENS * HDIM / 4 + 255) / 256, 256>>>(x, xh, TOKENS * HDIM / 4);
    cvt_h<<<(3 * HDIM * HDIM / 4 + 255) / 256, 256>>>(w_qkv, wqh, 3 * HDIM * HDIM / 4);
    cvt_h<<<(HDIM * HDIM / 4 + 255) / 256, 256>>>(w_o, woh, HDIM * HDIM / 4);

    // 1) QKV projection (fp16 tensor cores, 3-stage pipeline)
    cudaFuncSetAttribute(gemm_h_nt, cudaFuncAttributeMaxDynamicSharedMemorySize, 98304);
    gemm_h_nt<<<dim3(3 * HDIM / 128, TOKENS / 128), 128, 98304>>>(xh, wqh, qkv, TOKENS, 3 * HDIM, HDIM);

    // 2) RoPE + K fp16 frag-reorder + V fp16 pairing
    rope_kernel<<<(TOKENS * NH * 32) / 256, 256>>>(qkv, khp, vph);

    // 3) Causal flash attention (fp16) -> att fp16
    const int flash_smem = 2 * 64 * KH * 2 + 2 * 32 * VST * 4;  // 36864 B
    cudaFuncSetAttribute(flash2, cudaFuncAttributeMaxDynamicSharedMemorySize, flash_smem);
    flash2<<<dim3(S_LEN / 128, 2 * NH), 128, flash_smem>>>(qkv, khp, (const __half2*)vph, ath);

    // 4) Output projection (fp16 tensor cores)
    gemm_h_nt<<<dim3(HDIM / 128, TOKENS / 128), 128, 98304>>>(ath, woh, out, TOKENS, HDIM, HDIM);
}